// round 2
// baseline (speedup 1.0000x reference)
#include <cuda_runtime.h>
#include <cuda_bf16.h>
#include <math.h>

#define NN 200000
#define NE 800000
#define NG 8192
#define HD 200
#define NLAYERS 5
#define TSTEPS 2

// ------------------------- scratch (static device globals) -------------------------
__device__ float d_h[(size_t)NN * HD];
__device__ float d_e[(size_t)NE * HD];
__device__ float d_agg[(size_t)NN * HD];
__device__ float d_hv[(size_t)NN * HD];
__device__ float d_g[NG * HD];
__device__ float d_ctx[NG * HD];
__device__ float d_gi[NG * 600];
__device__ float d_gh[NG * 600];
__device__ float d_t1[NG * 1024];
__device__ float d_z[NN];
__device__ float d_aw[NN];
__device__ float d_zmax[NG];
__device__ float d_zden[NG];
__device__ int d_cnt[NN];
__device__ int d_rowptr[NN + 1];
__device__ int d_fill[NN];
__device__ int2 d_adj[NE];
__device__ int d_gcnt[NG];
__device__ int d_gptr[NG + 1];
__device__ int d_bsums[1024];

// ------------------------- small utility kernels -------------------------
__global__ void zero_int(int* p, int n) {
    int gid = blockIdx.x * blockDim.x + threadIdx.x;
    if (gid < n) p[gid] = 0;
}

__global__ void hist_kernel(const int* __restrict__ idx, int* __restrict__ cnt, int n) {
    int gid = blockIdx.x * blockDim.x + threadIdx.x;
    if (gid < n) atomicAdd(&cnt[idx[gid]], 1);
}

__global__ void scan1_kernel(const int* __restrict__ in, int* __restrict__ outp1,
                             int* __restrict__ bsums, int n) {
    __shared__ int sh[1024];
    int t = threadIdx.x;
    long base = (long)blockIdx.x * 8192 + (long)t * 8;
    int v[8];
    int run = 0;
#pragma unroll
    for (int i = 0; i < 8; i++) {
        long idx = base + i;
        int x = (idx < n) ? in[idx] : 0;
        run += x;
        v[i] = run;
    }
    sh[t] = run;
    __syncthreads();
    int total = run;
    for (int off = 1; off < 1024; off <<= 1) {
        int y = (t >= off) ? sh[t - off] : 0;
        __syncthreads();
        sh[t] += y;
        __syncthreads();
    }
    int excl = sh[t] - total;
#pragma unroll
    for (int i = 0; i < 8; i++) {
        long idx = base + i;
        if (idx < n) outp1[idx + 1] = v[i] + excl;
    }
    if (t == 1023) bsums[blockIdx.x] = sh[1023];
    if (blockIdx.x == 0 && t == 0) outp1[0] = 0;
}

__global__ void scan2_kernel(int* bsums, int nb) {
    __shared__ int sh[1024];
    int t = threadIdx.x;
    int v = (t < nb) ? bsums[t] : 0;
    sh[t] = v;
    __syncthreads();
    for (int off = 1; off < 1024; off <<= 1) {
        int y = (t >= off) ? sh[t - off] : 0;
        __syncthreads();
        sh[t] += y;
        __syncthreads();
    }
    if (t < nb) bsums[t] = sh[t] - v;  // exclusive
}

__global__ void scan3_kernel(int* outp1, const int* __restrict__ bsums, int n) {
    int gid = blockIdx.x * blockDim.x + threadIdx.x;
    if (gid < n) outp1[gid + 1] += bsums[gid >> 13];
}

__global__ void copy_int(const int* __restrict__ a, int* __restrict__ b, int n) {
    int gid = blockIdx.x * blockDim.x + threadIdx.x;
    if (gid < n) b[gid] = a[gid];
}

__global__ void fill_adj_kernel(const int* __restrict__ src, const int* __restrict__ dst,
                                int* __restrict__ fill, int2* __restrict__ adj, int n) {
    int gid = blockIdx.x * blockDim.x + threadIdx.x;
    if (gid < n) {
        int d = dst[gid];
        int pos = atomicAdd(&fill[d], 1);
        adj[pos] = make_int2(src[gid], gid);
    }
}

// ------------------------- bf16x3 tensor-core GEMM -------------------------
// C[M,NCOL] = epilogue(A[M,K] @ W[K,NCOL] + bias), fp32 in/out.
// Split each fp32 into bf16 hi+lo; acc += Ah*Wh + Ah*Wl + Al*Wh (fp32 accum).
// Tile: BM=128 rows x BNT=208 cols, BK=32. 256 threads = 8 warps (4 m x 2 n).
// mode 0: C = acc + bias;  mode 1: C = relu(acc+bias)*ls[col] + C (residual)
#define GBM 128
#define GBK 32
#define GBK2 16      // GBK/2 (k-pairs)
#define GBNT 208     // col tile (13 n8-tiles per warp-col x 2 warp-cols)
#define GBNP 216     // padded smem stride for W (216 % 32 == 24 -> conflict-free)

__device__ __forceinline__ void mma16816(float* c, unsigned a0, unsigned a1,
                                         unsigned a2, unsigned a3,
                                         unsigned b0, unsigned b1) {
    asm volatile(
        "mma.sync.aligned.m16n8k16.row.col.f32.bf16.bf16.f32 "
        "{%0,%1,%2,%3}, {%4,%5,%6,%7}, {%8,%9}, {%0,%1,%2,%3};\n"
        : "+f"(c[0]), "+f"(c[1]), "+f"(c[2]), "+f"(c[3])
        : "r"(a0), "r"(a1), "r"(a2), "r"(a3), "r"(b0), "r"(b1));
}

__device__ __forceinline__ unsigned pack_bf16(float x, float y) {
    unsigned short lo = __bfloat16_as_ushort(__float2bfloat16(x));
    unsigned short hi = __bfloat16_as_ushort(__float2bfloat16(y));
    return ((unsigned)hi << 16) | (unsigned)lo;
}

__global__ __launch_bounds__(256) void mma_gemm_kernel(
    const float* __restrict__ A, const float* __restrict__ W,
    const float* __restrict__ bias, float* __restrict__ C,
    int M, int K, int NCOL, int ldw, int ldc, int mode, const float* __restrict__ ls) {
    // smem: k-pair packed bf16x2 fragments, hi and lo planes
    __shared__ unsigned Aps[2][GBM][GBK2 + 1];   // [hi/lo][row][kpair]
    __shared__ unsigned Wps[2][GBK2][GBNP];      // [hi/lo][kpair][col]

    int tid = threadIdx.x;
    int wid = tid >> 5;
    int lane = tid & 31;
    int g = lane >> 2;       // group id 0..7
    int t = lane & 3;        // thread-in-group 0..3
    int warp_m = wid & 3;    // 0..3  (32 rows each)
    int warp_n = wid >> 2;   // 0..1  (104 cols each)
    int row0 = blockIdx.x * GBM;
    int col0 = blockIdx.y * GBNT;

    float acc[2][13][4];
#pragma unroll
    for (int s = 0; s < 2; s++)
#pragma unroll
        for (int nt = 0; nt < 13; nt++)
#pragma unroll
            for (int i = 0; i < 4; i++) acc[s][nt][i] = 0.f;

    for (int k0 = 0; k0 < K; k0 += GBK) {
        // ---- load + split A tile: 128 rows x 16 k-pairs ----
#pragma unroll
        for (int p = tid; p < GBM * GBK2; p += 256) {
            int m = p >> 4;
            int i = p & 15;
            int gr = row0 + m;
            int k = k0 + 2 * i;
            float v0 = 0.f, v1 = 0.f;
            if (gr < M) {
                if (k < K) v0 = A[(long)gr * K + k];
                if (k + 1 < K) v1 = A[(long)gr * K + k + 1];
            }
            float h0 = __bfloat162float(__float2bfloat16(v0));
            float h1 = __bfloat162float(__float2bfloat16(v1));
            Aps[0][m][i] = pack_bf16(h0, h1);
            Aps[1][m][i] = pack_bf16(v0 - h0, v1 - h1);
        }
        // ---- load + split W tile: 16 k-pairs x 208 cols ----
        for (int p = tid; p < GBK2 * GBNT; p += 256) {
            int kk2 = p / GBNT;
            int n = p - kk2 * GBNT;
            int gn = col0 + n;
            int k = k0 + 2 * kk2;
            float v0 = 0.f, v1 = 0.f;
            if (gn < NCOL) {
                if (k < K) v0 = W[(long)k * ldw + gn];
                if (k + 1 < K) v1 = W[(long)(k + 1) * ldw + gn];
            }
            float h0 = __bfloat162float(__float2bfloat16(v0));
            float h1 = __bfloat162float(__float2bfloat16(v1));
            Wps[0][kk2][n] = pack_bf16(h0, h1);
            Wps[1][kk2][n] = pack_bf16(v0 - h0, v1 - h1);
        }
        __syncthreads();

#pragma unroll
        for (int ks = 0; ks < 2; ks++) {   // two k16 steps per tile
            int kb = ks * 8;               // kpair base
            // A fragments for the two m16 sub-tiles, hi and lo
            unsigned ah[2][4], al[2][4];
#pragma unroll
            for (int s = 0; s < 2; s++) {
                int r = warp_m * 32 + s * 16 + g;
                ah[s][0] = Aps[0][r][kb + t];
                ah[s][1] = Aps[0][r + 8][kb + t];
                ah[s][2] = Aps[0][r][kb + 4 + t];
                ah[s][3] = Aps[0][r + 8][kb + 4 + t];
                al[s][0] = Aps[1][r][kb + t];
                al[s][1] = Aps[1][r + 8][kb + t];
                al[s][2] = Aps[1][r][kb + 4 + t];
                al[s][3] = Aps[1][r + 8][kb + 4 + t];
            }
#pragma unroll
            for (int nt = 0; nt < 13; nt++) {
                int n = warp_n * 104 + nt * 8 + g;
                unsigned bh0 = Wps[0][kb + t][n];
                unsigned bh1 = Wps[0][kb + 4 + t][n];
                unsigned bl0 = Wps[1][kb + t][n];
                unsigned bl1 = Wps[1][kb + 4 + t][n];
#pragma unroll
                for (int s = 0; s < 2; s++) {
                    mma16816(acc[s][nt], ah[s][0], ah[s][1], ah[s][2], ah[s][3], bh0, bh1);
                    mma16816(acc[s][nt], ah[s][0], ah[s][1], ah[s][2], ah[s][3], bl0, bl1);
                    mma16816(acc[s][nt], al[s][0], al[s][1], al[s][2], al[s][3], bh0, bh1);
                }
            }
        }
        __syncthreads();
    }

    // ---- epilogue ----
#pragma unroll
    for (int s = 0; s < 2; s++) {
        int rbase = row0 + warp_m * 32 + s * 16 + g;
#pragma unroll
        for (int nt = 0; nt < 13; nt++) {
            int cbase = col0 + warp_n * 104 + nt * 8 + 2 * t;
#pragma unroll
            for (int half = 0; half < 2; half++) {   // rows g, g+8
                int gr = rbase + half * 8;
                if (gr >= M) continue;
#pragma unroll
                for (int cc = 0; cc < 2; cc++) {
                    int gc = cbase + cc;
                    if (gc >= NCOL) continue;
                    float v = acc[s][nt][half * 2 + cc] + (bias ? bias[gc] : 0.f);
                    long off = (long)gr * ldc + gc;
                    if (mode == 1) v = fmaxf(v, 0.f) * ls[gc] + C[off];
                    C[off] = v;
                }
            }
        }
    }
}

// ------------------------- message passing: fused gather + edge softmax + agg -------------------------
__global__ void msg_kernel(const float* __restrict__ h, const float* __restrict__ e,
                           const int* __restrict__ rowptr, const int2* __restrict__ adj,
                           float* __restrict__ agg) {
    long gid = (long)blockIdx.x * blockDim.x + threadIdx.x;
    if (gid >= (long)NN * HD) return;
    int v = (int)(gid / HD);
    int f = (int)(gid - (long)v * HD);
    int b = rowptr[v], en = rowptr[v + 1];
    float mx = -3.4e38f, den = 0.f, acc = 0.f;
    for (int p = b; p < en; p++) {
        int2 se = adj[p];
        float m = h[(long)se.x * HD + f] + e[(long)se.y * HD + f];
        if (m > mx) {
            float sc = __expf(mx - m);
            den *= sc;
            acc *= sc;
            mx = m;
        }
        float pz = __expf(m - mx);
        den += pz;
        acc += pz * m;
    }
    agg[gid] = (den > 0.f) ? acc / den : 0.f;
}

// ------------------------- graph readout kernels -------------------------
__global__ void gsum_kernel(const float* __restrict__ h, const int* __restrict__ gptr,
                            float* __restrict__ g) {
    int gid = blockIdx.x * blockDim.x + threadIdx.x;
    if (gid >= NG * HD) return;
    int gg = gid / HD;
    int f = gid - gg * HD;
    int b = gptr[gg], e = gptr[gg + 1];
    float s = 0.f;
    for (int n = b; n < e; n++) s += h[(long)n * HD + f];
    g[gid] = s;
}

__global__ void z_kernel(const float* __restrict__ h, const float* __restrict__ g,
                         const int* __restrict__ n2g, const float* __restrict__ lw,
                         const float* __restrict__ lb, float* __restrict__ z) {
    int warp = (blockIdx.x * blockDim.x + threadIdx.x) >> 5;
    int lane = threadIdx.x & 31;
    if (warp >= NN) return;
    int gg = n2g[warp];
    const float* grow = g + (long)gg * HD;
    const float* hrow = h + (long)warp * HD;
    float s = 0.f;
    for (int f = lane; f < HD; f += 32)
        s += fmaxf(grow[f], 0.f) * lw[f] + hrow[f] * lw[HD + f];
#pragma unroll
    for (int o = 16; o; o >>= 1) s += __shfl_xor_sync(0xffffffffu, s, o);
    if (lane == 0) {
        float v = s + lb[0];
        z[warp] = (v > 0.f) ? v : 0.01f * v;  // leaky_relu
    }
}

__global__ void attn_kernel(const float* __restrict__ z, const int* __restrict__ gptr,
                            float* __restrict__ zmax, float* __restrict__ zden) {
    int warp = (blockIdx.x * blockDim.x + threadIdx.x) >> 5;
    int lane = threadIdx.x & 31;
    if (warp >= NG) return;
    int b = gptr[warp], e = gptr[warp + 1];
    float mx = -3.4e38f;
    for (int i = b + lane; i < e; i += 32) mx = fmaxf(mx, z[i]);
#pragma unroll
    for (int o = 16; o; o >>= 1) mx = fmaxf(mx, __shfl_xor_sync(0xffffffffu, mx, o));
    float s = 0.f;
    for (int i = b + lane; i < e; i += 32) s += __expf(z[i] - mx);
#pragma unroll
    for (int o = 16; o; o >>= 1) s += __shfl_xor_sync(0xffffffffu, s, o);
    if (lane == 0) {
        zmax[warp] = mx;
        zden[warp] = s;
    }
}

__global__ void a_kernel(const float* __restrict__ z, const int* __restrict__ n2g,
                         const float* __restrict__ zmax, const float* __restrict__ zden,
                         float* __restrict__ a) {
    int gid = blockIdx.x * blockDim.x + threadIdx.x;
    if (gid >= NN) return;
    int gg = n2g[gid];
    a[gid] = __expf(z[gid] - zmax[gg]) / zden[gg];
}

__global__ void ctx_kernel(const float* __restrict__ hv, const float* __restrict__ a,
                           const int* __restrict__ gptr, float* __restrict__ ctx) {
    int gid = blockIdx.x * blockDim.x + threadIdx.x;
    if (gid >= NG * HD) return;
    int gg = gid / HD;
    int f = gid - gg * HD;
    int b = gptr[gg], e = gptr[gg + 1];
    float s = 0.f;
    for (int n = b; n < e; n++) s += hv[(long)n * HD + f] * a[n];
    ctx[gid] = (s > 0.f) ? s : (__expf(s) - 1.f);  // elu
}

__global__ void gru_kernel(const float* __restrict__ gi, const float* __restrict__ gh,
                           float* __restrict__ g) {
    int gid = blockIdx.x * blockDim.x + threadIdx.x;
    if (gid >= NG * HD) return;
    int gg = gid / HD;
    int f = gid - gg * HD;
    const float* gib = gi + gg * 600;
    const float* ghb = gh + gg * 600;
    float r = 1.f / (1.f + __expf(-(gib[f] + ghb[f])));
    float u = 1.f / (1.f + __expf(-(gib[200 + f] + ghb[200 + f])));
    float nn = tanhf(gib[400 + f] + r * ghb[400 + f]);
    g[gid] = (1.f - u) * nn + u * g[gid];
}

__global__ void out2_kernel(const float* __restrict__ tmp, const float* __restrict__ w2,
                            const float* __restrict__ b2, float* __restrict__ out) {
    int warp = (blockIdx.x * blockDim.x + threadIdx.x) >> 5;
    int lane = threadIdx.x & 31;
    if (warp >= NG) return;
    float s = 0.f;
    const float* row = tmp + (long)warp * 1024;
    for (int c = lane; c < 1024; c += 32) s += fmaxf(row[c], 0.f) * w2[c];
#pragma unroll
    for (int o = 16; o; o >>= 1) s += __shfl_xor_sync(0xffffffffu, s, o);
    if (lane == 0) out[warp] = s + b2[0];
}

// ------------------------- launch -------------------------
extern "C" void kernel_launch(void* const* d_in, const int* in_sizes, int n_in,
                              void* d_out, int out_size) {
    const float* node_feats = (const float*)d_in[0];
    const float* edge_feats = (const float*)d_in[1];
    const int* src = (const int*)d_in[2];
    const int* dst = (const int*)d_in[3];
    const int* n2g = (const int*)d_in[4];
    const float* atom_W = (const float*)d_in[5];
    const float* atom_b = (const float*)d_in[6];
    const float* bond_W = (const float*)d_in[7];
    const float* bond_b = (const float*)d_in[8];
    const float* mlp_W = (const float*)d_in[9];
    const float* mlp_b = (const float*)d_in[10];
    const float* ls = (const float*)d_in[11];
    const float* logit_W = (const float*)d_in[12];
    const float* logit_b = (const float*)d_in[13];
    const float* proj_W = (const float*)d_in[14];
    const float* proj_b = (const float*)d_in[15];
    const float* gru_Wih = (const float*)d_in[16];
    const float* gru_Whh = (const float*)d_in[17];
    const float* gru_bih = (const float*)d_in[18];
    const float* gru_bhh = (const float*)d_in[19];
    const float* out1_W = (const float*)d_in[20];
    const float* out1_b = (const float*)d_in[21];
    const float* out2_W = (const float*)d_in[22];
    const float* out2_b = (const float*)d_in[23];
    float* out = (float*)d_out;

    float *ph, *pe, *pagg, *phv, *pg, *pctx, *pgi, *pgh, *pt1, *pz, *paw, *pzmax, *pzden;
    int *pcnt, *prow, *pfill, *pgcnt, *pgptr, *pbs;
    int2* padj;
    cudaGetSymbolAddress((void**)&ph, d_h);
    cudaGetSymbolAddress((void**)&pe, d_e);
    cudaGetSymbolAddress((void**)&pagg, d_agg);
    cudaGetSymbolAddress((void**)&phv, d_hv);
    cudaGetSymbolAddress((void**)&pg, d_g);
    cudaGetSymbolAddress((void**)&pctx, d_ctx);
    cudaGetSymbolAddress((void**)&pgi, d_gi);
    cudaGetSymbolAddress((void**)&pgh, d_gh);
    cudaGetSymbolAddress((void**)&pt1, d_t1);
    cudaGetSymbolAddress((void**)&pz, d_z);
    cudaGetSymbolAddress((void**)&paw, d_aw);
    cudaGetSymbolAddress((void**)&pzmax, d_zmax);
    cudaGetSymbolAddress((void**)&pzden, d_zden);
    cudaGetSymbolAddress((void**)&pcnt, d_cnt);
    cudaGetSymbolAddress((void**)&prow, d_rowptr);
    cudaGetSymbolAddress((void**)&pfill, d_fill);
    cudaGetSymbolAddress((void**)&pgcnt, d_gcnt);
    cudaGetSymbolAddress((void**)&pgptr, d_gptr);
    cudaGetSymbolAddress((void**)&pbs, d_bsums);
    cudaGetSymbolAddress((void**)&padj, d_adj);

    // ---- CSR by dst ----
    zero_int<<<(NN + 255) / 256, 256>>>(pcnt, NN);
    hist_kernel<<<(NE + 255) / 256, 256>>>(dst, pcnt, NE);
    int nb1 = (NN + 8191) / 8192;
    scan1_kernel<<<nb1, 1024>>>(pcnt, prow, pbs, NN);
    scan2_kernel<<<1, 1024>>>(pbs, nb1);
    scan3_kernel<<<(NN + 255) / 256, 256>>>(prow, pbs, NN);
    copy_int<<<(NN + 255) / 256, 256>>>(prow, pfill, NN);
    fill_adj_kernel<<<(NE + 255) / 256, 256>>>(src, dst, pfill, padj, NE);

    // ---- graph offsets ----
    zero_int<<<(NG + 255) / 256, 256>>>(pgcnt, NG);
    hist_kernel<<<(NN + 255) / 256, 256>>>(n2g, pgcnt, NN);
    scan1_kernel<<<1, 1024>>>(pgcnt, pgptr, pbs, NG);
    scan2_kernel<<<1, 1024>>>(pbs, 1);
    scan3_kernel<<<(NG + 255) / 256, 256>>>(pgptr, pbs, NG);

    // ---- encoders (tensor-core) ----
    dim3 gN((NN + GBM - 1) / GBM, (HD + GBNT - 1) / GBNT);
    dim3 gE((NE + GBM - 1) / GBM, (HD + GBNT - 1) / GBNT);
    mma_gemm_kernel<<<gN, 256>>>(node_feats, atom_W, atom_b, ph, NN, 74, HD, HD, HD, 0, nullptr);
    mma_gemm_kernel<<<gE, 256>>>(edge_feats, bond_W, bond_b, pe, NE, 12, HD, HD, HD, 0, nullptr);

    // ---- message passing layers ----
    long nthr = (long)NN * HD;
    int mblocks = (int)((nthr + 255) / 256);
    for (int i = 0; i < NLAYERS; i++) {
        msg_kernel<<<mblocks, 256>>>(ph, pe, prow, padj, pagg);
        mma_gemm_kernel<<<gN, 256>>>(pagg, mlp_W + (size_t)i * HD * HD, mlp_b + i * HD, ph,
                                     NN, HD, HD, HD, HD, 1, ls + i * HD);
    }

    // ---- readout ----
    gsum_kernel<<<(NG * HD + 255) / 256, 256>>>(ph, pgptr, pg);
    dim3 gG((NG + GBM - 1) / GBM, (600 + GBNT - 1) / GBNT);
    for (int t = 0; t < TSTEPS; t++) {
        z_kernel<<<(NN * 32 + 255) / 256, 256>>>(ph, pg, n2g, logit_W + t * 2 * HD,
                                                 logit_b + t, pz);
        attn_kernel<<<(NG * 32 + 255) / 256, 256>>>(pz, pgptr, pzmax, pzden);
        a_kernel<<<(NN + 255) / 256, 256>>>(pz, n2g, pzmax, pzden, paw);
        mma_gemm_kernel<<<gN, 256>>>(ph, proj_W + (size_t)t * HD * HD, proj_b + t * HD, phv,
                                     NN, HD, HD, HD, HD, 0, nullptr);
        ctx_kernel<<<(NG * HD + 255) / 256, 256>>>(phv, paw, pgptr, pctx);
        mma_gemm_kernel<<<gG, 256>>>(pctx, gru_Wih + (size_t)t * HD * 600, gru_bih + t * 600,
                                     pgi, NG, HD, 600, 600, 600, 0, nullptr);
        mma_gemm_kernel<<<gG, 256>>>(pg, gru_Whh + (size_t)t * HD * 600, gru_bhh + t * 600,
                                     pgh, NG, HD, 600, 600, 600, 0, nullptr);
        gru_kernel<<<(NG * HD + 255) / 256, 256>>>(pgi, pgh, pg);
    }

    dim3 gO((NG + GBM - 1) / GBM, (1024 + GBNT - 1) / GBNT);
    mma_gemm_kernel<<<gO, 256>>>(pg, out1_W, out1_b, pt1, NG, HD, 1024, 1024, 1024, 0, nullptr);
    out2_kernel<<<(NG * 32 + 255) / 256, 256>>>(pt1, out2_W, out2_b, out);
}

// round 4
// speedup vs baseline: 1.6450x; 1.6450x over previous
#include <cuda_runtime.h>
#include <cuda_bf16.h>
#include <math.h>
#include <cstdint>

#define NN 200000
#define NE 800000
#define NG 8192
#define HD 200
#define NLAYERS 5
#define TSTEPS 2

// ------------------------- scratch (static device globals) -------------------------
__device__ float d_h[(size_t)NN * HD];
__device__ float d_e[(size_t)NE * HD];
__device__ float d_agg[(size_t)NN * HD];
__device__ float d_hv[(size_t)NN * HD];
__device__ float d_g[NG * HD];
__device__ float d_ctx[NG * HD];
__device__ float d_gi[NG * 600];
__device__ float d_gh[NG * 600];
__device__ float d_t1[NG * 1024];
__device__ float d_z[NN];
__device__ float d_aw[NN];
__device__ float d_zmax[NG];
__device__ float d_zden[NG];
__device__ int d_cnt[NN];
__device__ int d_rowptr[NN + 1];
__device__ int d_fill[NN];
__device__ int2 d_adj[NE];
__device__ int d_gcnt[NG];
__device__ int d_gptr[NG + 1];
__device__ int d_bsums[1024];
// pre-transposed + bf16-split weights: [1040 rows (N, padded), 256 cols (K, padded)]
__device__ __nv_bfloat16 d_wth[1040 * 256];
__device__ __nv_bfloat16 d_wtl[1040 * 256];

// ------------------------- helpers -------------------------
__device__ __forceinline__ uint32_t smem_u32(const void* p) {
    uint32_t a;
    asm("{ .reg .u64 t; cvta.to.shared.u64 t, %1; cvt.u32.u64 %0, t; }" : "=r"(a) : "l"(p));
    return a;
}

__device__ __forceinline__ void mma16816(float* c, unsigned a0, unsigned a1,
                                         unsigned a2, unsigned a3,
                                         unsigned b0, unsigned b1) {
    asm volatile(
        "mma.sync.aligned.m16n8k16.row.col.f32.bf16.bf16.f32 "
        "{%0,%1,%2,%3}, {%4,%5,%6,%7}, {%8,%9}, {%0,%1,%2,%3};\n"
        : "+f"(c[0]), "+f"(c[1]), "+f"(c[2]), "+f"(c[3])
        : "r"(a0), "r"(a1), "r"(a2), "r"(a3), "r"(b0), "r"(b1));
}

#define LDSM_X4(r, a) \
    asm volatile("ldmatrix.sync.aligned.m8n8.x4.shared.b16 {%0,%1,%2,%3}, [%4];" \
                 : "=r"((r)[0]), "=r"((r)[1]), "=r"((r)[2]), "=r"((r)[3]) : "r"(a))
#define LDSM_X2(r, a) \
    asm volatile("ldmatrix.sync.aligned.m8n8.x2.shared.b16 {%0,%1}, [%2];" \
                 : "=r"((r)[0]), "=r"((r)[1]) : "r"(a))

__device__ __forceinline__ unsigned pack2(__nv_bfloat16 a, __nv_bfloat16 b) {
    return ((unsigned)__bfloat16_as_ushort(b) << 16) | (unsigned)__bfloat16_as_ushort(a);
}

// ------------------------- weight transpose + bf16 split -------------------------
// Wt[n][k] = W[k*ldw + n] split into hi/lo bf16; zero padded to [1040][256].
__global__ void wconv_kernel(const float* __restrict__ W, int K, int NCOL, int ldw,
                             __nv_bfloat16* __restrict__ wh, __nv_bfloat16* __restrict__ wl) {
    int gid = blockIdx.x * blockDim.x + threadIdx.x;
    if (gid >= 1040 * 256) return;
    int n = gid >> 8;
    int k = gid & 255;
    float v = (n < NCOL && k < K) ? W[(long)k * ldw + n] : 0.f;
    __nv_bfloat16 h = __float2bfloat16(v);
    wh[gid] = h;
    wl[gid] = __float2bfloat16(v - __bfloat162float(h));
}

// ------------------------- bf16x3 tensor-core GEMM (ldmatrix + swizzle) -------------------------
// C[M,NCOL] = epilogue(A[M,K] @ W[K,NCOL] + bias); A fp32 row-major,
// W pre-transposed/split in Bh/Bl [1040][256].
// Block tile 128 x 208, BK=32, 256 thr = 8 warps (4m x 2n, warp tile 32 x 104).
// mode 0: C = acc + bias; mode 1: C = relu(acc+bias)*ls[col] + C (residual in-place).
__global__ __launch_bounds__(256) void mma_gemm2(
    const float* __restrict__ A, const __nv_bfloat16* __restrict__ Bh,
    const __nv_bfloat16* __restrict__ Bl, const float* __restrict__ bias,
    float* __restrict__ C, int M, int K, int NCOL, int ldc, int mode,
    const float* __restrict__ ls) {
    // row = m (A) or n (B); 4 uint4 units per row = 32 k bf16. XOR swizzle:
    // physical unit = u ^ ((row>>1)&3)  -> conflict-free ldmatrix.
    __shared__ uint4 smA[2][128][4];   // [hi/lo][row][unit]
    __shared__ uint4 smB[2][208][4];

    int tid = threadIdx.x;
    int wid = tid >> 5;
    int lane = tid & 31;
    int warp_m = wid & 3;
    int warp_n = wid >> 2;
    int row0 = blockIdx.x * 128;
    int col0 = blockIdx.y * 208;

    float acc[2][13][4];
#pragma unroll
    for (int s = 0; s < 2; s++)
#pragma unroll
        for (int nt = 0; nt < 13; nt++)
#pragma unroll
            for (int i = 0; i < 4; i++) acc[s][nt][i] = 0.f;

    int nch = (K + 31) >> 5;
    for (int c = 0; c < nch; c++) {
        int k0 = c << 5;
        // ---- stage A: 128 rows x 32 k, fp32 -> bf16 hi/lo ----
#pragma unroll
        for (int p = tid; p < 512; p += 256) {
            int r = p >> 2;
            int u = p & 3;
            int gr = row0 + r;
            int kb = k0 + u * 8;
            float v[8];
#pragma unroll
            for (int j = 0; j < 8; j++) {
                int k = kb + j;
                v[j] = (gr < M && k < K) ? A[(long)gr * K + k] : 0.f;
            }
            unsigned hw[4], lw[4];
#pragma unroll
            for (int j = 0; j < 4; j++) {
                __nv_bfloat16 h0 = __float2bfloat16(v[2 * j]);
                __nv_bfloat16 h1 = __float2bfloat16(v[2 * j + 1]);
                __nv_bfloat16 l0 = __float2bfloat16(v[2 * j] - __bfloat162float(h0));
                __nv_bfloat16 l1 = __float2bfloat16(v[2 * j + 1] - __bfloat162float(h1));
                hw[j] = pack2(h0, h1);
                lw[j] = pack2(l0, l1);
            }
            int up = u ^ ((r >> 1) & 3);
            smA[0][r][up] = make_uint4(hw[0], hw[1], hw[2], hw[3]);
            smA[1][r][up] = make_uint4(lw[0], lw[1], lw[2], lw[3]);
        }
        // ---- stage B: 208 n-rows x 32 k (bf16, already split/padded) ----
#pragma unroll
        for (int p = tid; p < 832; p += 256) {
            int r = p >> 2;
            int u = p & 3;
            long src = (long)(col0 + r) * 256 + k0 + u * 8;
            int up = u ^ ((r >> 1) & 3);
            smB[0][r][up] = *(const uint4*)(Bh + src);
            smB[1][r][up] = *(const uint4*)(Bl + src);
        }
        __syncthreads();

#pragma unroll
        for (int kh = 0; kh < 2; kh++) {
            // A fragments (2 m16 sub-tiles, hi+lo planes)
            unsigned ah[2][4], al[2][4];
#pragma unroll
            for (int s = 0; s < 2; s++) {
                int r = warp_m * 32 + s * 16 + (lane & 15);
                int u = kh * 2 + (lane >> 4);
                int up = u ^ ((r >> 1) & 3);
                LDSM_X4(ah[s], smem_u32(&smA[0][r][up]));
                LDSM_X4(al[s], smem_u32(&smA[1][r][up]));
            }
            int nb = warp_n * 104;
            // 6 pairs of n8 tiles via x4
#pragma unroll
            for (int i = 0; i < 6; i++) {
                int r = nb + i * 16 + (lane & 7) + ((lane >> 4) << 3);
                int u = kh * 2 + ((lane >> 3) & 1);
                int up = u ^ ((r >> 1) & 3);
                unsigned bh[4], bl[4];
                LDSM_X4(bh, smem_u32(&smB[0][r][up]));
                LDSM_X4(bl, smem_u32(&smB[1][r][up]));
#pragma unroll
                for (int s = 0; s < 2; s++) {
                    mma16816(acc[s][2 * i], ah[s][0], ah[s][1], ah[s][2], ah[s][3], bh[0], bh[1]);
                    mma16816(acc[s][2 * i], ah[s][0], ah[s][1], ah[s][2], ah[s][3], bl[0], bl[1]);
                    mma16816(acc[s][2 * i], al[s][0], al[s][1], al[s][2], al[s][3], bh[0], bh[1]);
                    mma16816(acc[s][2 * i + 1], ah[s][0], ah[s][1], ah[s][2], ah[s][3], bh[2], bh[3]);
                    mma16816(acc[s][2 * i + 1], ah[s][0], ah[s][1], ah[s][2], ah[s][3], bl[2], bl[3]);
                    mma16816(acc[s][2 * i + 1], al[s][0], al[s][1], al[s][2], al[s][3], bh[2], bh[3]);
                }
            }
            // last n8 tile (nt = 12) via x2
            {
                int r = nb + 96 + (lane & 7);
                int u = kh * 2 + ((lane >> 3) & 1);
                int up = u ^ ((r >> 1) & 3);
                unsigned bh[2], bl[2];
                LDSM_X2(bh, smem_u32(&smB[0][r][up]));
                LDSM_X2(bl, smem_u32(&smB[1][r][up]));
#pragma unroll
                for (int s = 0; s < 2; s++) {
                    mma16816(acc[s][12], ah[s][0], ah[s][1], ah[s][2], ah[s][3], bh[0], bh[1]);
                    mma16816(acc[s][12], ah[s][0], ah[s][1], ah[s][2], ah[s][3], bl[0], bl[1]);
                    mma16816(acc[s][12], al[s][0], al[s][1], al[s][2], al[s][3], bh[0], bh[1]);
                }
            }
        }
        __syncthreads();
    }

    // ---- epilogue ----
#pragma unroll
    for (int s = 0; s < 2; s++) {
        int grb = row0 + warp_m * 32 + s * 16 + (lane >> 2);
#pragma unroll
        for (int nt = 0; nt < 13; nt++) {
            int gc = col0 + warp_n * 104 + nt * 8 + (lane & 3) * 2;
#pragma unroll
            for (int half = 0; half < 2; half++) {
                int gr = grb + half * 8;
                if (gr >= M) continue;
                float* crow = C + (long)gr * ldc;
#pragma unroll
                for (int cc = 0; cc < 2; cc++) {
                    int c2 = gc + cc;
                    if (c2 >= NCOL) continue;
                    float v = acc[s][nt][half * 2 + cc] + (bias ? bias[c2] : 0.f);
                    if (mode == 1) v = fmaxf(v, 0.f) * ls[c2] + crow[c2];
                    crow[c2] = v;
                }
            }
        }
    }
}

// ------------------------- small utility kernels -------------------------
__global__ void zero_int(int* p, int n) {
    int gid = blockIdx.x * blockDim.x + threadIdx.x;
    if (gid < n) p[gid] = 0;
}

__global__ void hist_kernel(const int* __restrict__ idx, int* __restrict__ cnt, int n) {
    int gid = blockIdx.x * blockDim.x + threadIdx.x;
    if (gid < n) atomicAdd(&cnt[idx[gid]], 1);
}

__global__ void scan1_kernel(const int* __restrict__ in, int* __restrict__ outp1,
                             int* __restrict__ bsums, int n) {
    __shared__ int sh[1024];
    int t = threadIdx.x;
    long base = (long)blockIdx.x * 8192 + (long)t * 8;
    int v[8];
    int run = 0;
#pragma unroll
    for (int i = 0; i < 8; i++) {
        long idx = base + i;
        int x = (idx < n) ? in[idx] : 0;
        run += x;
        v[i] = run;
    }
    sh[t] = run;
    __syncthreads();
    int total = run;
    for (int off = 1; off < 1024; off <<= 1) {
        int y = (t >= off) ? sh[t - off] : 0;
        __syncthreads();
        sh[t] += y;
        __syncthreads();
    }
    int excl = sh[t] - total;
#pragma unroll
    for (int i = 0; i < 8; i++) {
        long idx = base + i;
        if (idx < n) outp1[idx + 1] = v[i] + excl;
    }
    if (t == 1023) bsums[blockIdx.x] = sh[1023];
    if (blockIdx.x == 0 && t == 0) outp1[0] = 0;
}

__global__ void scan2_kernel(int* bsums, int nb) {
    __shared__ int sh[1024];
    int t = threadIdx.x;
    int v = (t < nb) ? bsums[t] : 0;
    sh[t] = v;
    __syncthreads();
    for (int off = 1; off < 1024; off <<= 1) {
        int y = (t >= off) ? sh[t - off] : 0;
        __syncthreads();
        sh[t] += y;
        __syncthreads();
    }
    if (t < nb) bsums[t] = sh[t] - v;  // exclusive
}

__global__ void scan3_kernel(int* outp1, const int* __restrict__ bsums, int n) {
    int gid = blockIdx.x * blockDim.x + threadIdx.x;
    if (gid < n) outp1[gid + 1] += bsums[gid >> 13];
}

__global__ void copy_int(const int* __restrict__ a, int* __restrict__ b, int n) {
    int gid = blockIdx.x * blockDim.x + threadIdx.x;
    if (gid < n) b[gid] = a[gid];
}

__global__ void fill_adj_kernel(const int* __restrict__ src, const int* __restrict__ dst,
                                int* __restrict__ fill, int2* __restrict__ adj, int n) {
    int gid = blockIdx.x * blockDim.x + threadIdx.x;
    if (gid < n) {
        int d = dst[gid];
        int pos = atomicAdd(&fill[d], 1);
        adj[pos] = make_int2(src[gid], gid);
    }
}

// ------------------------- message passing -------------------------
__global__ void msg_kernel(const float* __restrict__ h, const float* __restrict__ e,
                           const int* __restrict__ rowptr, const int2* __restrict__ adj,
                           float* __restrict__ agg) {
    long gid = (long)blockIdx.x * blockDim.x + threadIdx.x;
    if (gid >= (long)NN * HD) return;
    int v = (int)(gid / HD);
    int f = (int)(gid - (long)v * HD);
    int b = rowptr[v], en = rowptr[v + 1];
    float mx = -3.4e38f, den = 0.f, acc = 0.f;
    for (int p = b; p < en; p++) {
        int2 se = adj[p];
        float m = h[(long)se.x * HD + f] + e[(long)se.y * HD + f];
        if (m > mx) {
            float sc = __expf(mx - m);
            den *= sc;
            acc *= sc;
            mx = m;
        }
        float pz = __expf(m - mx);
        den += pz;
        acc += pz * m;
    }
    agg[gid] = (den > 0.f) ? acc / den : 0.f;
}

// ------------------------- graph readout kernels -------------------------
__global__ void gsum_kernel(const float* __restrict__ h, const int* __restrict__ gptr,
                            float* __restrict__ g) {
    int gid = blockIdx.x * blockDim.x + threadIdx.x;
    if (gid >= NG * HD) return;
    int gg = gid / HD;
    int f = gid - gg * HD;
    int b = gptr[gg], e = gptr[gg + 1];
    float s = 0.f;
    for (int n = b; n < e; n++) s += h[(long)n * HD + f];
    g[gid] = s;
}

__global__ void z_kernel(const float* __restrict__ h, const float* __restrict__ g,
                         const int* __restrict__ n2g, const float* __restrict__ lw,
                         const float* __restrict__ lb, float* __restrict__ z) {
    int warp = (blockIdx.x * blockDim.x + threadIdx.x) >> 5;
    int lane = threadIdx.x & 31;
    if (warp >= NN) return;
    int gg = n2g[warp];
    const float* grow = g + (long)gg * HD;
    const float* hrow = h + (long)warp * HD;
    float s = 0.f;
    for (int f = lane; f < HD; f += 32)
        s += fmaxf(grow[f], 0.f) * lw[f] + hrow[f] * lw[HD + f];
#pragma unroll
    for (int o = 16; o; o >>= 1) s += __shfl_xor_sync(0xffffffffu, s, o);
    if (lane == 0) {
        float v = s + lb[0];
        z[warp] = (v > 0.f) ? v : 0.01f * v;  // leaky_relu
    }
}

__global__ void attn_kernel(const float* __restrict__ z, const int* __restrict__ gptr,
                            float* __restrict__ zmax, float* __restrict__ zden) {
    int warp = (blockIdx.x * blockDim.x + threadIdx.x) >> 5;
    int lane = threadIdx.x & 31;
    if (warp >= NG) return;
    int b = gptr[warp], e = gptr[warp + 1];
    float mx = -3.4e38f;
    for (int i = b + lane; i < e; i += 32) mx = fmaxf(mx, z[i]);
#pragma unroll
    for (int o = 16; o; o >>= 1) mx = fmaxf(mx, __shfl_xor_sync(0xffffffffu, mx, o));
    float s = 0.f;
    for (int i = b + lane; i < e; i += 32) s += __expf(z[i] - mx);
#pragma unroll
    for (int o = 16; o; o >>= 1) s += __shfl_xor_sync(0xffffffffu, s, o);
    if (lane == 0) {
        zmax[warp] = mx;
        zden[warp] = s;
    }
}

__global__ void a_kernel(const float* __restrict__ z, const int* __restrict__ n2g,
                         const float* __restrict__ zmax, const float* __restrict__ zden,
                         float* __restrict__ a) {
    int gid = blockIdx.x * blockDim.x + threadIdx.x;
    if (gid >= NN) return;
    int gg = n2g[gid];
    a[gid] = __expf(z[gid] - zmax[gg]) / zden[gg];
}

__global__ void ctx_kernel(const float* __restrict__ hv, const float* __restrict__ a,
                           const int* __restrict__ gptr, float* __restrict__ ctx) {
    int gid = blockIdx.x * blockDim.x + threadIdx.x;
    if (gid >= NG * HD) return;
    int gg = gid / HD;
    int f = gid - gg * HD;
    int b = gptr[gg], e = gptr[gg + 1];
    float s = 0.f;
    for (int n = b; n < e; n++) s += hv[(long)n * HD + f] * a[n];
    ctx[gid] = (s > 0.f) ? s : (__expf(s) - 1.f);  // elu
}

__global__ void gru_kernel(const float* __restrict__ gi, const float* __restrict__ gh,
                           float* __restrict__ g) {
    int gid = blockIdx.x * blockDim.x + threadIdx.x;
    if (gid >= NG * HD) return;
    int gg = gid / HD;
    int f = gid - gg * HD;
    const float* gib = gi + gg * 600;
    const float* ghb = gh + gg * 600;
    float r = 1.f / (1.f + __expf(-(gib[f] + ghb[f])));
    float u = 1.f / (1.f + __expf(-(gib[200 + f] + ghb[200 + f])));
    float nn = tanhf(gib[400 + f] + r * ghb[400 + f]);
    g[gid] = (1.f - u) * nn + u * g[gid];
}

__global__ void out2_kernel(const float* __restrict__ tmp, const float* __restrict__ w2,
                            const float* __restrict__ b2, float* __restrict__ out) {
    int warp = (blockIdx.x * blockDim.x + threadIdx.x) >> 5;
    int lane = threadIdx.x & 31;
    if (warp >= NG) return;
    float s = 0.f;
    const float* row = tmp + (long)warp * 1024;
    for (int c = lane; c < 1024; c += 32) s += fmaxf(row[c], 0.f) * w2[c];
#pragma unroll
    for (int o = 16; o; o >>= 1) s += __shfl_xor_sync(0xffffffffu, s, o);
    if (lane == 0) out[warp] = s + b2[0];
}

// ------------------------- launch -------------------------
static void launch_gemm(const float* A, const float* W, int ldw, const float* bias,
                        float* C, int M, int K, int NCOL, int mode, const float* ls,
                        __nv_bfloat16* pwth, __nv_bfloat16* pwtl) {
    wconv_kernel<<<1040, 256>>>(W, K, NCOL, ldw, pwth, pwtl);
    dim3 grid((M + 127) / 128, (NCOL + 207) / 208);
    mma_gemm2<<<grid, 256>>>(A, pwth, pwtl, bias, C, M, K, NCOL, NCOL, mode, ls);
}

extern "C" void kernel_launch(void* const* d_in, const int* in_sizes, int n_in,
                              void* d_out, int out_size) {
    const float* node_feats = (const float*)d_in[0];
    const float* edge_feats = (const float*)d_in[1];
    const int* src = (const int*)d_in[2];
    const int* dst = (const int*)d_in[3];
    const int* n2g = (const int*)d_in[4];
    const float* atom_W = (const float*)d_in[5];
    const float* atom_b = (const float*)d_in[6];
    const float* bond_W = (const float*)d_in[7];
    const float* bond_b = (const float*)d_in[8];
    const float* mlp_W = (const float*)d_in[9];
    const float* mlp_b = (const float*)d_in[10];
    const float* ls = (const float*)d_in[11];
    const float* logit_W = (const float*)d_in[12];
    const float* logit_b = (const float*)d_in[13];
    const float* proj_W = (const float*)d_in[14];
    const float* proj_b = (const float*)d_in[15];
    const float* gru_Wih = (const float*)d_in[16];
    const float* gru_Whh = (const float*)d_in[17];
    const float* gru_bih = (const float*)d_in[18];
    const float* gru_bhh = (const float*)d_in[19];
    const float* out1_W = (const float*)d_in[20];
    const float* out1_b = (const float*)d_in[21];
    const float* out2_W = (const float*)d_in[22];
    const float* out2_b = (const float*)d_in[23];
    float* out = (float*)d_out;

    float *ph, *pe, *pagg, *phv, *pg, *pctx, *pgi, *pgh, *pt1, *pz, *paw, *pzmax, *pzden;
    int *pcnt, *prow, *pfill, *pgcnt, *pgptr, *pbs;
    int2* padj;
    __nv_bfloat16 *pwth, *pwtl;
    cudaGetSymbolAddress((void**)&ph, d_h);
    cudaGetSymbolAddress((void**)&pe, d_e);
    cudaGetSymbolAddress((void**)&pagg, d_agg);
    cudaGetSymbolAddress((void**)&phv, d_hv);
    cudaGetSymbolAddress((void**)&pg, d_g);
    cudaGetSymbolAddress((void**)&pctx, d_ctx);
    cudaGetSymbolAddress((void**)&pgi, d_gi);
    cudaGetSymbolAddress((void**)&pgh, d_gh);
    cudaGetSymbolAddress((void**)&pt1, d_t1);
    cudaGetSymbolAddress((void**)&pz, d_z);
    cudaGetSymbolAddress((void**)&paw, d_aw);
    cudaGetSymbolAddress((void**)&pzmax, d_zmax);
    cudaGetSymbolAddress((void**)&pzden, d_zden);
    cudaGetSymbolAddress((void**)&pcnt, d_cnt);
    cudaGetSymbolAddress((void**)&prow, d_rowptr);
    cudaGetSymbolAddress((void**)&pfill, d_fill);
    cudaGetSymbolAddress((void**)&pgcnt, d_gcnt);
    cudaGetSymbolAddress((void**)&pgptr, d_gptr);
    cudaGetSymbolAddress((void**)&pbs, d_bsums);
    cudaGetSymbolAddress((void**)&padj, d_adj);
    cudaGetSymbolAddress((void**)&pwth, d_wth);
    cudaGetSymbolAddress((void**)&pwtl, d_wtl);

    // ---- CSR by dst ----
    zero_int<<<(NN + 255) / 256, 256>>>(pcnt, NN);
    hist_kernel<<<(NE + 255) / 256, 256>>>(dst, pcnt, NE);
    int nb1 = (NN + 8191) / 8192;
    scan1_kernel<<<nb1, 1024>>>(pcnt, prow, pbs, NN);
    scan2_kernel<<<1, 1024>>>(pbs, nb1);
    scan3_kernel<<<(NN + 255) / 256, 256>>>(prow, pbs, NN);
    copy_int<<<(NN + 255) / 256, 256>>>(prow, pfill, NN);
    fill_adj_kernel<<<(NE + 255) / 256, 256>>>(src, dst, pfill, padj, NE);

    // ---- graph offsets ----
    zero_int<<<(NG + 255) / 256, 256>>>(pgcnt, NG);
    hist_kernel<<<(NN + 255) / 256, 256>>>(n2g, pgcnt, NN);
    scan1_kernel<<<1, 1024>>>(pgcnt, pgptr, pbs, NG);
    scan2_kernel<<<1, 1024>>>(pbs, 1);
    scan3_kernel<<<(NG + 255) / 256, 256>>>(pgptr, pbs, NG);

    // ---- encoders ----
    launch_gemm(node_feats, atom_W, HD, atom_b, ph, NN, 74, HD, 0, nullptr, pwth, pwtl);
    launch_gemm(edge_feats, bond_W, HD, bond_b, pe, NE, 12, HD, 0, nullptr, pwth, pwtl);

    // ---- message passing layers ----
    long nthr = (long)NN * HD;
    int mblocks = (int)((nthr + 255) / 256);
    for (int i = 0; i < NLAYERS; i++) {
        msg_kernel<<<mblocks, 256>>>(ph, pe, prow, padj, pagg);
        launch_gemm(pagg, mlp_W + (size_t)i * HD * HD, HD, mlp_b + i * HD, ph,
                    NN, HD, HD, 1, ls + i * HD, pwth, pwtl);
    }

    // ---- readout ----
    gsum_kernel<<<(NG * HD + 255) / 256, 256>>>(ph, pgptr, pg);
    for (int t = 0; t < TSTEPS; t++) {
        z_kernel<<<(NN * 32 + 255) / 256, 256>>>(ph, pg, n2g, logit_W + t * 2 * HD,
                                                 logit_b + t, pz);
        attn_kernel<<<(NG * 32 + 255) / 256, 256>>>(pz, pgptr, pzmax, pzden);
        a_kernel<<<(NN + 255) / 256, 256>>>(pz, n2g, pzmax, pzden, paw);
        launch_gemm(ph, proj_W + (size_t)t * HD * HD, HD, proj_b + t * HD, phv,
                    NN, HD, HD, 0, nullptr, pwth, pwtl);
        ctx_kernel<<<(NG * HD + 255) / 256, 256>>>(phv, paw, pgptr, pctx);
        launch_gemm(pctx, gru_Wih + (size_t)t * HD * 600, 600, gru_bih + t * 600,
                    pgi, NG, HD, 600, 0, nullptr, pwth, pwtl);
        launch_gemm(pg, gru_Whh + (size_t)t * HD * 600, 600, gru_bhh + t * 600,
                    pgh, NG, HD, 600, 0, nullptr, pwth, pwtl);
        gru_kernel<<<(NG * HD + 255) / 256, 256>>>(pgi, pgh, pg);
    }

    launch_gemm(pg, out1_W, 1024, out1_b, pt1, NG, HD, 1024, 0, nullptr, pwth, pwtl);
    out2_kernel<<<(NG * 32 + 255) / 256, 256>>>(pt1, out2_W, out2_b, out);
}

// round 5
// speedup vs baseline: 1.7227x; 1.0472x over previous
#include <cuda_runtime.h>
#include <cuda_bf16.h>
#include <math.h>
#include <cstdint>

#define NN 200000
#define NE 800000
#define NG 8192
#define HD 200
#define NLAYERS 5
#define TSTEPS 2

#define WSLOT (1040 * 256)
#define NSLOTS 14

// ------------------------- scratch (static device globals) -------------------------
__device__ float d_h[(size_t)NN * HD];
__device__ float d_e[(size_t)NE * HD];
__device__ float d_agg[(size_t)NN * HD];
__device__ float d_hv[(size_t)NN * HD];
__device__ float d_g[NG * HD];
__device__ float d_ctx[NG * HD];
__device__ float d_gi[NG * 600];
__device__ float d_gh[NG * 600];
__device__ float d_t1[NG * 1024];
__device__ float d_z[NN];
__device__ float d_zmax[NG];
__device__ float d_zden[NG];
__device__ int d_cnt[NN];
__device__ int d_rowptr[NN + 1];
__device__ int d_fill[NN];
__device__ int2 d_adj[NE];
__device__ int d_gcnt[NG];
__device__ int d_gptr[NG + 1];
__device__ int d_bsums[1024];
// all weights, pre-transposed + bf16-split: [slot][1040 n-rows][256 k]
__device__ __nv_bfloat16 d_wall_h[NSLOTS * WSLOT];
__device__ __nv_bfloat16 d_wall_l[NSLOTS * WSLOT];

// ------------------------- helpers -------------------------
__device__ __forceinline__ uint32_t smem_u32(const void* p) {
    uint32_t a;
    asm("{ .reg .u64 t; cvta.to.shared.u64 t, %1; cvt.u32.u64 %0, t; }" : "=r"(a) : "l"(p));
    return a;
}

__device__ __forceinline__ void mma16816(float* c, unsigned a0, unsigned a1,
                                         unsigned a2, unsigned a3,
                                         unsigned b0, unsigned b1) {
    asm volatile(
        "mma.sync.aligned.m16n8k16.row.col.f32.bf16.bf16.f32 "
        "{%0,%1,%2,%3}, {%4,%5,%6,%7}, {%8,%9}, {%0,%1,%2,%3};\n"
        : "+f"(c[0]), "+f"(c[1]), "+f"(c[2]), "+f"(c[3])
        : "r"(a0), "r"(a1), "r"(a2), "r"(a3), "r"(b0), "r"(b1));
}

#define LDSM_X4(r, a) \
    asm volatile("ldmatrix.sync.aligned.m8n8.x4.shared.b16 {%0,%1,%2,%3}, [%4];" \
                 : "=r"((r)[0]), "=r"((r)[1]), "=r"((r)[2]), "=r"((r)[3]) : "r"(a))
#define LDSM_X2(r, a) \
    asm volatile("ldmatrix.sync.aligned.m8n8.x2.shared.b16 {%0,%1}, [%2];" \
                 : "=r"((r)[0]), "=r"((r)[1]) : "r"(a))

#define CP16(dst, src, sz) \
    asm volatile("cp.async.ca.shared.global [%0], [%1], 16, %2;" \
                 :: "r"(dst), "l"(src), "r"(sz))
#define CP8(dst, src, sz) \
    asm volatile("cp.async.ca.shared.global [%0], [%1], 8, %2;" \
                 :: "r"(dst), "l"(src), "r"(sz))
#define CPCOMMIT() asm volatile("cp.async.commit_group;" ::: "memory")
#define CPWAIT1() asm volatile("cp.async.wait_group 1;" ::: "memory")
#define CPWAIT0() asm volatile("cp.async.wait_group 0;" ::: "memory")

__device__ __forceinline__ unsigned pack2(__nv_bfloat16 a, __nv_bfloat16 b) {
    return ((unsigned)__bfloat16_as_ushort(b) << 16) | (unsigned)__bfloat16_as_ushort(a);
}

// ------------------------- one-shot weight transpose + split -------------------------
struct WSlotDesc {
    const float* W;
    int K, NCOL, ldw;
};
struct WTable {
    WSlotDesc s[NSLOTS];
};

__global__ void wconv_all(WTable T, __nv_bfloat16* __restrict__ wh,
                          __nv_bfloat16* __restrict__ wl) {
    long gid = (long)blockIdx.x * blockDim.x + threadIdx.x;
    if (gid >= (long)NSLOTS * WSLOT) return;
    int slot = (int)(gid / WSLOT);
    int rem = (int)(gid - (long)slot * WSLOT);
    int n = rem >> 8;
    int k = rem & 255;
    WSlotDesc d = T.s[slot];
    float v = (n < d.NCOL && k < d.K) ? d.W[(long)k * d.ldw + n] : 0.f;
    __nv_bfloat16 h = __float2bfloat16(v);
    wh[gid] = h;
    wl[gid] = __float2bfloat16(v - __bfloat162float(h));
}

// ------------------------- pipelined bf16x3 tensor-core GEMM -------------------------
// C[M,NCOL] = epilogue(A[M,K] @ W[K,NCOL] + bias); A fp32 row-major, W via slot bank.
// Block 128x208, BK=32, 8 warps (4m x 2n, warp tile 32x104), cp.async double-buffered.
// dynamic smem layout (bytes):
#define SM_ARAW 0        // float[2][128][32]  = 32768
#define SM_A    32768    // uint4[2][128][4]   = 16384 (hi/lo planes)
#define SM_B    49152    // uint4[2][2][208][4]= 53248 (stage, hi/lo)
#define SM_TOT  102400

__global__ __launch_bounds__(256) void mma_gemm3(
    const float* __restrict__ A, const __nv_bfloat16* __restrict__ Bh,
    const __nv_bfloat16* __restrict__ Bl, const float* __restrict__ bias,
    float* __restrict__ C, int M, int K, int NCOL, int ldc, int mode,
    const float* __restrict__ ls) {
    extern __shared__ char sm[];
    float* araw = (float*)(sm + SM_ARAW);
    uint4* sA = (uint4*)(sm + SM_A);
    uint4* sB = (uint4*)(sm + SM_B);
    uint32_t smb = smem_u32(sm);

    int tid = threadIdx.x;
    int wid = tid >> 5;
    int lane = tid & 31;
    int warp_m = wid & 3;
    int warp_n = wid >> 2;
    int row0 = blockIdx.x * 128;
    int col0 = blockIdx.y * 208;
    bool al16 = ((K & 3) == 0);

    float acc[2][13][4];
#pragma unroll
    for (int s = 0; s < 2; s++)
#pragma unroll
        for (int nt = 0; nt < 13; nt++)
#pragma unroll
            for (int i = 0; i < 4; i++) acc[s][nt][i] = 0.f;

    int nch = (K + 31) >> 5;

    // ---- async load issue for chunk c into given stage ----
    auto issue_loads = [&](int c, int stage) {
        int k0 = c << 5;
        // A raw fp32: 128 rows x 32 k
#pragma unroll
        for (int p = tid; p < 512; p += 256) {
            int r = p >> 2;
            int u = p & 3;
            int gr = row0 + r;
            int kb = k0 + u * 8;
            uint32_t dst = smb + SM_ARAW +
                           (uint32_t)(stage * 4096 + r * 32 + ((u ^ (r & 3)) * 8)) * 4u;
            int grc = (gr < M) ? gr : 0;
            if (al16) {
#pragma unroll
                for (int j = 0; j < 2; j++) {
                    int kk = kb + j * 4;
                    int valid = (gr < M && kk < K) ? min(K - kk, 4) : 0;
                    const float* src = A + (size_t)grc * K + ((kk < K) ? kk : 0);
                    CP16(dst + j * 16, src, valid * 4);
                }
            } else {
#pragma unroll
                for (int j = 0; j < 4; j++) {
                    int kk = kb + j * 2;
                    int valid = (gr < M && kk < K) ? min(K - kk, 2) : 0;
                    const float* src = A + (size_t)grc * K + ((kk < K) ? kk : 0);
                    CP8(dst + j * 8, src, valid * 4);
                }
            }
        }
        // B bf16 (pre-padded, no predicates): 2 planes x 208 rows x 32 k
        for (int p = tid; p < 1664; p += 256) {
            int plane = p / 832;
            int rem = p - plane * 832;
            int r = rem >> 2;
            int u = rem & 3;
            const __nv_bfloat16* W = plane ? Bl : Bh;
            const __nv_bfloat16* src = W + (size_t)(col0 + r) * 256 + k0 + u * 8;
            uint32_t dst = smb + SM_B +
                           (uint32_t)(stage * 1664 + plane * 832 + r * 4 +
                                      (u ^ ((r >> 1) & 3))) * 16u;
            CP16(dst, src, 16);
        }
    };

    issue_loads(0, 0);
    CPCOMMIT();

    for (int c = 0; c < nch; c++) {
        int stage = c & 1;
        if (c + 1 < nch) {
            issue_loads(c + 1, stage ^ 1);
            CPCOMMIT();
            CPWAIT1();
        } else {
            CPWAIT0();
        }
        __syncthreads();

        // ---- convert araw[stage] -> sA (hi/lo bf16, ldmatrix swizzle) ----
#pragma unroll
        for (int p = tid; p < 512; p += 256) {
            int r = p >> 2;
            int u = p & 3;
            const float* f = araw + stage * 4096 + r * 32 + ((u ^ (r & 3)) * 8);
            unsigned hw[4], lw[4];
#pragma unroll
            for (int j = 0; j < 4; j++) {
                float v0 = f[2 * j], v1 = f[2 * j + 1];
                __nv_bfloat16 h0 = __float2bfloat16(v0);
                __nv_bfloat16 h1 = __float2bfloat16(v1);
                __nv_bfloat16 l0 = __float2bfloat16(v0 - __bfloat162float(h0));
                __nv_bfloat16 l1 = __float2bfloat16(v1 - __bfloat162float(h1));
                hw[j] = pack2(h0, h1);
                lw[j] = pack2(l0, l1);
            }
            int up = u ^ ((r >> 1) & 3);
            sA[r * 4 + up] = make_uint4(hw[0], hw[1], hw[2], hw[3]);
            sA[512 + r * 4 + up] = make_uint4(lw[0], lw[1], lw[2], lw[3]);
        }
        __syncthreads();

        // ---- MMA ----
        int bbase = stage * 1664;
#pragma unroll
        for (int kh = 0; kh < 2; kh++) {
            unsigned ah[2][4], al[2][4];
#pragma unroll
            for (int s = 0; s < 2; s++) {
                int r = warp_m * 32 + s * 16 + (lane & 15);
                int u = kh * 2 + (lane >> 4);
                int up = u ^ ((r >> 1) & 3);
                LDSM_X4(ah[s], smem_u32(&sA[r * 4 + up]));
                LDSM_X4(al[s], smem_u32(&sA[512 + r * 4 + up]));
            }
            int nb = warp_n * 104;
#pragma unroll
            for (int i = 0; i < 6; i++) {
                int r = nb + i * 16 + (lane & 7) + ((lane >> 4) << 3);
                int u = kh * 2 + ((lane >> 3) & 1);
                int up = u ^ ((r >> 1) & 3);
                unsigned bh[4], bl[4];
                LDSM_X4(bh, smem_u32(&sB[bbase + r * 4 + up]));
                LDSM_X4(bl, smem_u32(&sB[bbase + 832 + r * 4 + up]));
#pragma unroll
                for (int s = 0; s < 2; s++) {
                    mma16816(acc[s][2 * i], ah[s][0], ah[s][1], ah[s][2], ah[s][3], bh[0], bh[1]);
                    mma16816(acc[s][2 * i], ah[s][0], ah[s][1], ah[s][2], ah[s][3], bl[0], bl[1]);
                    mma16816(acc[s][2 * i], al[s][0], al[s][1], al[s][2], al[s][3], bh[0], bh[1]);
                    mma16816(acc[s][2 * i + 1], ah[s][0], ah[s][1], ah[s][2], ah[s][3], bh[2], bh[3]);
                    mma16816(acc[s][2 * i + 1], ah[s][0], ah[s][1], ah[s][2], ah[s][3], bl[2], bl[3]);
                    mma16816(acc[s][2 * i + 1], al[s][0], al[s][1], al[s][2], al[s][3], bh[2], bh[3]);
                }
            }
            {
                int r = nb + 96 + (lane & 7);
                int u = kh * 2 + ((lane >> 3) & 1);
                int up = u ^ ((r >> 1) & 3);
                unsigned bh[2], bl[2];
                LDSM_X2(bh, smem_u32(&sB[bbase + r * 4 + up]));
                LDSM_X2(bl, smem_u32(&sB[bbase + 832 + r * 4 + up]));
#pragma unroll
                for (int s = 0; s < 2; s++) {
                    mma16816(acc[s][12], ah[s][0], ah[s][1], ah[s][2], ah[s][3], bh[0], bh[1]);
                    mma16816(acc[s][12], ah[s][0], ah[s][1], ah[s][2], ah[s][3], bl[0], bl[1]);
                    mma16816(acc[s][12], al[s][0], al[s][1], al[s][2], al[s][3], bh[0], bh[1]);
                }
            }
        }
        __syncthreads();
    }

    // ---- epilogue ----
#pragma unroll
    for (int s = 0; s < 2; s++) {
        int grb = row0 + warp_m * 32 + s * 16 + (lane >> 2);
#pragma unroll
        for (int nt = 0; nt < 13; nt++) {
            int gc = col0 + warp_n * 104 + nt * 8 + (lane & 3) * 2;
#pragma unroll
            for (int half = 0; half < 2; half++) {
                int gr = grb + half * 8;
                if (gr >= M) continue;
                float* crow = C + (long)gr * ldc;
#pragma unroll
                for (int cc = 0; cc < 2; cc++) {
                    int c2 = gc + cc;
                    if (c2 >= NCOL) continue;
                    float v = acc[s][nt][half * 2 + cc] + (bias ? bias[c2] : 0.f);
                    if (mode == 1) v = fmaxf(v, 0.f) * ls[c2] + crow[c2];
                    crow[c2] = v;
                }
            }
        }
    }
}

// ------------------------- small utility kernels -------------------------
__global__ void zero_int(int* p, int n) {
    int gid = blockIdx.x * blockDim.x + threadIdx.x;
    if (gid < n) p[gid] = 0;
}

__global__ void hist_kernel(const int* __restrict__ idx, int* __restrict__ cnt, int n) {
    int gid = blockIdx.x * blockDim.x + threadIdx.x;
    if (gid < n) atomicAdd(&cnt[idx[gid]], 1);
}

__global__ void scan1_kernel(const int* __restrict__ in, int* __restrict__ outp1,
                             int* __restrict__ bsums, int n) {
    __shared__ int sh[1024];
    int t = threadIdx.x;
    long base = (long)blockIdx.x * 8192 + (long)t * 8;
    int v[8];
    int run = 0;
#pragma unroll
    for (int i = 0; i < 8; i++) {
        long idx = base + i;
        int x = (idx < n) ? in[idx] : 0;
        run += x;
        v[i] = run;
    }
    sh[t] = run;
    __syncthreads();
    int total = run;
    for (int off = 1; off < 1024; off <<= 1) {
        int y = (t >= off) ? sh[t - off] : 0;
        __syncthreads();
        sh[t] += y;
        __syncthreads();
    }
    int excl = sh[t] - total;
#pragma unroll
    for (int i = 0; i < 8; i++) {
        long idx = base + i;
        if (idx < n) outp1[idx + 1] = v[i] + excl;
    }
    if (t == 1023) bsums[blockIdx.x] = sh[1023];
    if (blockIdx.x == 0 && t == 0) outp1[0] = 0;
}

__global__ void scan2_kernel(int* bsums, int nb) {
    __shared__ int sh[1024];
    int t = threadIdx.x;
    int v = (t < nb) ? bsums[t] : 0;
    sh[t] = v;
    __syncthreads();
    for (int off = 1; off < 1024; off <<= 1) {
        int y = (t >= off) ? sh[t - off] : 0;
        __syncthreads();
        sh[t] += y;
        __syncthreads();
    }
    if (t < nb) bsums[t] = sh[t] - v;  // exclusive
}

__global__ void scan3_kernel(int* outp1, const int* __restrict__ bsums, int n) {
    int gid = blockIdx.x * blockDim.x + threadIdx.x;
    if (gid < n) outp1[gid + 1] += bsums[gid >> 13];
}

__global__ void copy_int(const int* __restrict__ a, int* __restrict__ b, int n) {
    int gid = blockIdx.x * blockDim.x + threadIdx.x;
    if (gid < n) b[gid] = a[gid];
}

__global__ void fill_adj_kernel(const int* __restrict__ src, const int* __restrict__ dst,
                                int* __restrict__ fill, int2* __restrict__ adj, int n) {
    int gid = blockIdx.x * blockDim.x + threadIdx.x;
    if (gid < n) {
        int d = dst[gid];
        int pos = atomicAdd(&fill[d], 1);
        adj[pos] = make_int2(src[gid], gid);
    }
}

// ------------------------- message passing -------------------------
__global__ void msg_kernel(const float* __restrict__ h, const float* __restrict__ e,
                           const int* __restrict__ rowptr, const int2* __restrict__ adj,
                           float* __restrict__ agg) {
    long gid = (long)blockIdx.x * blockDim.x + threadIdx.x;
    if (gid >= (long)NN * HD) return;
    int v = (int)(gid / HD);
    int f = (int)(gid - (long)v * HD);
    int b = rowptr[v], en = rowptr[v + 1];
    float mx = -3.4e38f, den = 0.f, acc = 0.f;
    for (int p = b; p < en; p++) {
        int2 se = adj[p];
        float m = h[(long)se.x * HD + f] + e[(long)se.y * HD + f];
        if (m > mx) {
            float sc = __expf(mx - m);
            den *= sc;
            acc *= sc;
            mx = m;
        }
        float pz = __expf(m - mx);
        den += pz;
        acc += pz * m;
    }
    agg[gid] = (den > 0.f) ? acc / den : 0.f;
}

// ------------------------- graph readout kernels -------------------------
__global__ void gsum_kernel(const float* __restrict__ h, const int* __restrict__ gptr,
                            float* __restrict__ g) {
    int gid = blockIdx.x * blockDim.x + threadIdx.x;
    if (gid >= NG * HD) return;
    int gg = gid / HD;
    int f = gid - gg * HD;
    int b = gptr[gg], e = gptr[gg + 1];
    float s = 0.f;
    for (int n = b; n < e; n++) s += h[(long)n * HD + f];
    g[gid] = s;
}

__global__ void z_kernel(const float* __restrict__ h, const float* __restrict__ g,
                         const int* __restrict__ n2g, const float* __restrict__ lw,
                         const float* __restrict__ lb, float* __restrict__ z) {
    int warp = (blockIdx.x * blockDim.x + threadIdx.x) >> 5;
    int lane = threadIdx.x & 31;
    if (warp >= NN) return;
    int gg = n2g[warp];
    const float* grow = g + (long)gg * HD;
    const float* hrow = h + (long)warp * HD;
    float s = 0.f;
    for (int f = lane; f < HD; f += 32)
        s += fmaxf(grow[f], 0.f) * lw[f] + hrow[f] * lw[HD + f];
#pragma unroll
    for (int o = 16; o; o >>= 1) s += __shfl_xor_sync(0xffffffffu, s, o);
    if (lane == 0) {
        float v = s + lb[0];
        z[warp] = (v > 0.f) ? v : 0.01f * v;  // leaky_relu
    }
}

__global__ void attn_kernel(const float* __restrict__ z, const int* __restrict__ gptr,
                            float* __restrict__ zmax, float* __restrict__ zden) {
    int warp = (blockIdx.x * blockDim.x + threadIdx.x) >> 5;
    int lane = threadIdx.x & 31;
    if (warp >= NG) return;
    int b = gptr[warp], e = gptr[warp + 1];
    float mx = -3.4e38f;
    for (int i = b + lane; i < e; i += 32) mx = fmaxf(mx, z[i]);
#pragma unroll
    for (int o = 16; o; o >>= 1) mx = fmaxf(mx, __shfl_xor_sync(0xffffffffu, mx, o));
    float s = 0.f;
    for (int i = b + lane; i < e; i += 32) s += __expf(z[i] - mx);
#pragma unroll
    for (int o = 16; o; o >>= 1) s += __shfl_xor_sync(0xffffffffu, s, o);
    if (lane == 0) {
        zmax[warp] = mx;
        zden[warp] = s;
    }
}

// ctx with attention weight computed inline (a_kernel fused away)
__global__ void ctx_kernel(const float* __restrict__ hv, const float* __restrict__ z,
                           const float* __restrict__ zmax, const float* __restrict__ zden,
                           const int* __restrict__ gptr, float* __restrict__ ctx) {
    int gid = blockIdx.x * blockDim.x + threadIdx.x;
    if (gid >= NG * HD) return;
    int gg = gid / HD;
    int f = gid - gg * HD;
    int b = gptr[gg], e = gptr[gg + 1];
    float zm = zmax[gg];
    float inv = 1.f / zden[gg];
    float s = 0.f;
    for (int n = b; n < e; n++)
        s += hv[(long)n * HD + f] * (__expf(z[n] - zm) * inv);
    ctx[gid] = (s > 0.f) ? s : (__expf(s) - 1.f);  // elu
}

__global__ void gru_kernel(const float* __restrict__ gi, const float* __restrict__ gh,
                           float* __restrict__ g) {
    int gid = blockIdx.x * blockDim.x + threadIdx.x;
    if (gid >= NG * HD) return;
    int gg = gid / HD;
    int f = gid - gg * HD;
    const float* gib = gi + gg * 600;
    const float* ghb = gh + gg * 600;
    float r = 1.f / (1.f + __expf(-(gib[f] + ghb[f])));
    float u = 1.f / (1.f + __expf(-(gib[200 + f] + ghb[200 + f])));
    float nn = tanhf(gib[400 + f] + r * ghb[400 + f]);
    g[gid] = (1.f - u) * nn + u * g[gid];
}

__global__ void out2_kernel(const float* __restrict__ tmp, const float* __restrict__ w2,
                            const float* __restrict__ b2, float* __restrict__ out) {
    int warp = (blockIdx.x * blockDim.x + threadIdx.x) >> 5;
    int lane = threadIdx.x & 31;
    if (warp >= NG) return;
    float s = 0.f;
    const float* row = tmp + (long)warp * 1024;
    for (int c = lane; c < 1024; c += 32) s += fmaxf(row[c], 0.f) * w2[c];
#pragma unroll
    for (int o = 16; o; o >>= 1) s += __shfl_xor_sync(0xffffffffu, s, o);
    if (lane == 0) out[warp] = s + b2[0];
}

// ------------------------- launch -------------------------
static __nv_bfloat16 *g_pwh, *g_pwl;

static void launch_gemm(int slot, const float* A, const float* bias, float* C,
                        int M, int K, int NCOL, int mode, const float* ls) {
    dim3 grid((M + 127) / 128, (NCOL + 207) / 208);
    mma_gemm3<<<grid, 256, SM_TOT>>>(A, g_pwh + (size_t)slot * WSLOT,
                                     g_pwl + (size_t)slot * WSLOT, bias, C, M, K,
                                     NCOL, NCOL, mode, ls);
}

extern "C" void kernel_launch(void* const* d_in, const int* in_sizes, int n_in,
                              void* d_out, int out_size) {
    const float* node_feats = (const float*)d_in[0];
    const float* edge_feats = (const float*)d_in[1];
    const int* src = (const int*)d_in[2];
    const int* dst = (const int*)d_in[3];
    const int* n2g = (const int*)d_in[4];
    const float* atom_W = (const float*)d_in[5];
    const float* atom_b = (const float*)d_in[6];
    const float* bond_W = (const float*)d_in[7];
    const float* bond_b = (const float*)d_in[8];
    const float* mlp_W = (const float*)d_in[9];
    const float* mlp_b = (const float*)d_in[10];
    const float* ls = (const float*)d_in[11];
    const float* logit_W = (const float*)d_in[12];
    const float* logit_b = (const float*)d_in[13];
    const float* proj_W = (const float*)d_in[14];
    const float* proj_b = (const float*)d_in[15];
    const float* gru_Wih = (const float*)d_in[16];
    const float* gru_Whh = (const float*)d_in[17];
    const float* gru_bih = (const float*)d_in[18];
    const float* gru_bhh = (const float*)d_in[19];
    const float* out1_W = (const float*)d_in[20];
    const float* out1_b = (const float*)d_in[21];
    const float* out2_W = (const float*)d_in[22];
    const float* out2_b = (const float*)d_in[23];
    float* out = (float*)d_out;

    cudaFuncSetAttribute(mma_gemm3, cudaFuncAttributeMaxDynamicSharedMemorySize, SM_TOT);

    float *ph, *pe, *pagg, *phv, *pg, *pctx, *pgi, *pgh, *pt1, *pz, *pzmax, *pzden;
    int *pcnt, *prow, *pfill, *pgcnt, *pgptr, *pbs;
    int2* padj;
    cudaGetSymbolAddress((void**)&ph, d_h);
    cudaGetSymbolAddress((void**)&pe, d_e);
    cudaGetSymbolAddress((void**)&pagg, d_agg);
    cudaGetSymbolAddress((void**)&phv, d_hv);
    cudaGetSymbolAddress((void**)&pg, d_g);
    cudaGetSymbolAddress((void**)&pctx, d_ctx);
    cudaGetSymbolAddress((void**)&pgi, d_gi);
    cudaGetSymbolAddress((void**)&pgh, d_gh);
    cudaGetSymbolAddress((void**)&pt1, d_t1);
    cudaGetSymbolAddress((void**)&pz, d_z);
    cudaGetSymbolAddress((void**)&pzmax, d_zmax);
    cudaGetSymbolAddress((void**)&pzden, d_zden);
    cudaGetSymbolAddress((void**)&pcnt, d_cnt);
    cudaGetSymbolAddress((void**)&prow, d_rowptr);
    cudaGetSymbolAddress((void**)&pfill, d_fill);
    cudaGetSymbolAddress((void**)&pgcnt, d_gcnt);
    cudaGetSymbolAddress((void**)&pgptr, d_gptr);
    cudaGetSymbolAddress((void**)&pbs, d_bsums);
    cudaGetSymbolAddress((void**)&padj, d_adj);
    cudaGetSymbolAddress((void**)&g_pwh, d_wall_h);
    cudaGetSymbolAddress((void**)&g_pwl, d_wall_l);

    // ---- slot table ----
    WTable T;
    T.s[0] = {atom_W, 74, HD, HD};
    T.s[1] = {bond_W, 12, HD, HD};
    for (int i = 0; i < NLAYERS; i++) T.s[2 + i] = {mlp_W + (size_t)i * HD * HD, HD, HD, HD};
    for (int t = 0; t < TSTEPS; t++) {
        T.s[7 + t] = {proj_W + (size_t)t * HD * HD, HD, HD, HD};
        T.s[9 + t] = {gru_Wih + (size_t)t * HD * 600, HD, 600, 600};
        T.s[11 + t] = {gru_Whh + (size_t)t * HD * 600, HD, 600, 600};
    }
    T.s[13] = {out1_W, HD, 1024, 1024};

    // launch order chosen so the node-encoder GEMM is our 4th launch (ncu capture)
    wconv_all<<<(NSLOTS * WSLOT + 255) / 256, 256>>>(T, g_pwh, g_pwl);       // 1
    zero_int<<<(NN + 255) / 256, 256>>>(pcnt, NN);                           // 2
    hist_kernel<<<(NE + 255) / 256, 256>>>(dst, pcnt, NE);                   // 3
    launch_gemm(0, node_feats, atom_b, ph, NN, 74, HD, 0, nullptr);          // 4 <- capture
    launch_gemm(1, edge_feats, bond_b, pe, NE, 12, HD, 0, nullptr);          // 5

    // ---- CSR by dst (cont.) ----
    int nb1 = (NN + 8191) / 8192;
    scan1_kernel<<<nb1, 1024>>>(pcnt, prow, pbs, NN);
    scan2_kernel<<<1, 1024>>>(pbs, nb1);
    scan3_kernel<<<(NN + 255) / 256, 256>>>(prow, pbs, NN);
    copy_int<<<(NN + 255) / 256, 256>>>(prow, pfill, NN);
    fill_adj_kernel<<<(NE + 255) / 256, 256>>>(src, dst, pfill, padj, NE);

    // ---- graph offsets ----
    zero_int<<<(NG + 255) / 256, 256>>>(pgcnt, NG);
    hist_kernel<<<(NN + 255) / 256, 256>>>(n2g, pgcnt, NN);
    scan1_kernel<<<1, 1024>>>(pgcnt, pgptr, pbs, NG);
    scan2_kernel<<<1, 1024>>>(pbs, 1);
    scan3_kernel<<<(NG + 255) / 256, 256>>>(pgptr, pbs, NG);

    // ---- message passing layers ----
    long nthr = (long)NN * HD;
    int mblocks = (int)((nthr + 255) / 256);
    for (int i = 0; i < NLAYERS; i++) {
        msg_kernel<<<mblocks, 256>>>(ph, pe, prow, padj, pagg);
        launch_gemm(2 + i, pagg, mlp_b + i * HD, ph, NN, HD, HD, 1, ls + i * HD);
    }

    // ---- readout ----
    gsum_kernel<<<(NG * HD + 255) / 256, 256>>>(ph, pgptr, pg);
    for (int t = 0; t < TSTEPS; t++) {
        z_kernel<<<(NN * 32 + 255) / 256, 256>>>(ph, pg, n2g, logit_W + t * 2 * HD,
                                                 logit_b + t, pz);
        attn_kernel<<<(NG * 32 + 255) / 256, 256>>>(pz, pgptr, pzmax, pzden);
        launch_gemm(7 + t, ph, proj_b + t * HD, phv, NN, HD, HD, 0, nullptr);
        ctx_kernel<<<(NG * HD + 255) / 256, 256>>>(phv, pz, pzmax, pzden, pgptr, pctx);
        launch_gemm(9 + t, pctx, gru_bih + t * 600, pgi, NG, HD, 600, 0, nullptr);
        launch_gemm(11 + t, pg, gru_bhh + t * 600, pgh, NG, HD, 600, 0, nullptr);
        gru_kernel<<<(NG * HD + 255) / 256, 256>>>(pgi, pgh, pg);
    }

    launch_gemm(13, pg, out1_b, pt1, NG, HD, 1024, 0, nullptr);
    out2_kernel<<<(NG * 32 + 255) / 256, 256>>>(pt1, out2_W, out2_b, out);
}

// round 6
// speedup vs baseline: 2.1079x; 1.2236x over previous
#include <cuda_runtime.h>
#include <cuda_bf16.h>
#include <cuda_fp16.h>
#include <math.h>
#include <cstdint>

#define NN 200000
#define NE 800000
#define NG 8192
#define HD 200
#define NLAYERS 5
#define TSTEPS 2

#define WSLOT (1040 * 256)
#define NSLOTS 14

// ------------------------- scratch (static device globals) -------------------------
__device__ float d_h[(size_t)NN * HD];
__device__ float d_e[(size_t)NE * HD];
__device__ float d_agg[(size_t)NN * HD];
__device__ float d_hv[(size_t)NN * HD];
__device__ float d_g[NG * HD];
__device__ float d_ctx[NG * HD];
__device__ float d_gi[NG * 600];
__device__ float d_gh[NG * 600];
__device__ float d_t1[NG * 1024];
__device__ float d_z[NN];
__device__ float d_zmax[NG];
__device__ float d_zden[NG];
__device__ int d_cnt[NN];
__device__ int d_rowptr[NN + 1];
__device__ int d_fill[NN];
__device__ int2 d_adj[NE];
__device__ int d_gcnt[NG];
__device__ int d_gptr[NG + 1];
__device__ int d_bsums[1024];
// fp16 mirrors for message passing
__device__ __half d_h16[(size_t)NN * HD];
__device__ __half d_e16[(size_t)NE * HD];
// all weights, pre-transposed + bf16-split: [slot][1040 n-rows][256 k]
__device__ __nv_bfloat16 d_wall_h[NSLOTS * WSLOT];
__device__ __nv_bfloat16 d_wall_l[NSLOTS * WSLOT];

// ------------------------- helpers -------------------------
__device__ __forceinline__ uint32_t smem_u32(const void* p) {
    uint32_t a;
    asm("{ .reg .u64 t; cvta.to.shared.u64 t, %1; cvt.u32.u64 %0, t; }" : "=r"(a) : "l"(p));
    return a;
}

__device__ __forceinline__ void mma16816(float* c, unsigned a0, unsigned a1,
                                         unsigned a2, unsigned a3,
                                         unsigned b0, unsigned b1) {
    asm volatile(
        "mma.sync.aligned.m16n8k16.row.col.f32.bf16.bf16.f32 "
        "{%0,%1,%2,%3}, {%4,%5,%6,%7}, {%8,%9}, {%0,%1,%2,%3};\n"
        : "+f"(c[0]), "+f"(c[1]), "+f"(c[2]), "+f"(c[3])
        : "r"(a0), "r"(a1), "r"(a2), "r"(a3), "r"(b0), "r"(b1));
}

#define LDSM_X4(r, a) \
    asm volatile("ldmatrix.sync.aligned.m8n8.x4.shared.b16 {%0,%1,%2,%3}, [%4];" \
                 : "=r"((r)[0]), "=r"((r)[1]), "=r"((r)[2]), "=r"((r)[3]) : "r"(a))

#define CP16(dst, src, sz) \
    asm volatile("cp.async.ca.shared.global [%0], [%1], 16, %2;" \
                 :: "r"(dst), "l"(src), "r"(sz))
#define CP8(dst, src, sz) \
    asm volatile("cp.async.ca.shared.global [%0], [%1], 8, %2;" \
                 :: "r"(dst), "l"(src), "r"(sz))
#define CPCOMMIT() asm volatile("cp.async.commit_group;" ::: "memory")
#define CPWAIT1() asm volatile("cp.async.wait_group 1;" ::: "memory")
#define CPWAIT0() asm volatile("cp.async.wait_group 0;" ::: "memory")

__device__ __forceinline__ unsigned pack2(__nv_bfloat16 a, __nv_bfloat16 b) {
    return ((unsigned)__bfloat16_as_ushort(b) << 16) | (unsigned)__bfloat16_as_ushort(a);
}

// ------------------------- one-shot weight transpose + split -------------------------
struct WSlotDesc {
    const float* W;
    int K, NCOL, ldw;
};
struct WTable {
    WSlotDesc s[NSLOTS];
};

__global__ void wconv_all(WTable T, __nv_bfloat16* __restrict__ wh,
                          __nv_bfloat16* __restrict__ wl) {
    long gid = (long)blockIdx.x * blockDim.x + threadIdx.x;
    if (gid >= (long)NSLOTS * WSLOT) return;
    int slot = (int)(gid / WSLOT);
    int rem = (int)(gid - (long)slot * WSLOT);
    int n = rem >> 8;
    int k = rem & 255;
    WSlotDesc d = T.s[slot];
    float v = (n < d.NCOL && k < d.K) ? d.W[(long)k * d.ldw + n] : 0.f;
    __nv_bfloat16 h = __float2bfloat16(v);
    wh[gid] = h;
    wl[gid] = __float2bfloat16(v - __bfloat162float(h));
}

// ------------------------- pipelined bf16x3 tensor-core GEMM (2 CTA/SM) -------------------------
// Block 128x128, BK=32, 8 warps (4m x 2n, warp tile 32x64), cp.async double-buffered.
// mode 0: C = acc + bias; mode 1: C = relu(acc+bias)*ls[col] + C (residual).
// out16 != nullptr: also write half copy of C.
#define SM_ARAW 0        // float[2][128][32]  = 32768
#define SM_A    32768    // uint4[2][128][4]   = 16384 (hi/lo planes)
#define SM_B    49152    // uint4[2][2][128][4]= 32768 (stage, hi/lo)
#define SM_TOT  81920

__global__ __launch_bounds__(256, 2) void mma_gemm4(
    const float* __restrict__ A, const __nv_bfloat16* __restrict__ Bh,
    const __nv_bfloat16* __restrict__ Bl, const float* __restrict__ bias,
    float* __restrict__ C, int M, int K, int NCOL, int ldc, int mode,
    const float* __restrict__ ls, __half* __restrict__ out16) {
    extern __shared__ char sm[];
    float* araw = (float*)(sm + SM_ARAW);
    uint4* sA = (uint4*)(sm + SM_A);
    uint4* sB = (uint4*)(sm + SM_B);
    uint32_t smb = smem_u32(sm);

    int tid = threadIdx.x;
    int wid = tid >> 5;
    int lane = tid & 31;
    int warp_m = wid & 3;
    int warp_n = wid >> 2;
    int row0 = blockIdx.x * 128;
    int col0 = blockIdx.y * 128;
    bool al16 = ((K & 3) == 0);

    float acc[2][8][4];
#pragma unroll
    for (int s = 0; s < 2; s++)
#pragma unroll
        for (int nt = 0; nt < 8; nt++)
#pragma unroll
            for (int i = 0; i < 4; i++) acc[s][nt][i] = 0.f;

    int nch = (K + 31) >> 5;

    auto issue_loads = [&](int c, int stage) {
        int k0 = c << 5;
        // A raw fp32: 128 rows x 32 k
#pragma unroll
        for (int p = tid; p < 512; p += 256) {
            int r = p >> 2;
            int u = p & 3;
            int gr = row0 + r;
            int kb = k0 + u * 8;
            uint32_t dst = smb + SM_ARAW +
                           (uint32_t)(stage * 4096 + r * 32 + ((u ^ (r & 3)) * 8)) * 4u;
            int grc = (gr < M) ? gr : 0;
            if (al16) {
#pragma unroll
                for (int j = 0; j < 2; j++) {
                    int kk = kb + j * 4;
                    int valid = (gr < M && kk < K) ? min(K - kk, 4) : 0;
                    const float* src = A + (size_t)grc * K + ((kk < K) ? kk : 0);
                    CP16(dst + j * 16, src, valid * 4);
                }
            } else {
#pragma unroll
                for (int j = 0; j < 4; j++) {
                    int kk = kb + j * 2;
                    int valid = (gr < M && kk < K) ? min(K - kk, 2) : 0;
                    const float* src = A + (size_t)grc * K + ((kk < K) ? kk : 0);
                    CP8(dst + j * 8, src, valid * 4);
                }
            }
        }
        // B bf16 (pre-padded): 2 planes x 128 rows x 32 k
#pragma unroll
        for (int p = tid; p < 1024; p += 256) {
            int plane = p >> 9;
            int rem = p & 511;
            int r = rem >> 2;
            int u = rem & 3;
            const __nv_bfloat16* W = plane ? Bl : Bh;
            const __nv_bfloat16* src = W + (size_t)(col0 + r) * 256 + k0 + u * 8;
            uint32_t dst = smb + SM_B +
                           (uint32_t)(stage * 1024 + plane * 512 + r * 4 +
                                      (u ^ ((r >> 1) & 3))) * 16u;
            CP16(dst, src, 16);
        }
    };

    issue_loads(0, 0);
    CPCOMMIT();

    for (int c = 0; c < nch; c++) {
        int stage = c & 1;
        if (c + 1 < nch) {
            issue_loads(c + 1, stage ^ 1);
            CPCOMMIT();
            CPWAIT1();
        } else {
            CPWAIT0();
        }
        __syncthreads();

        // convert araw[stage] -> sA (hi/lo bf16)
#pragma unroll
        for (int p = tid; p < 512; p += 256) {
            int r = p >> 2;
            int u = p & 3;
            const float* f = araw + stage * 4096 + r * 32 + ((u ^ (r & 3)) * 8);
            unsigned hw[4], lw[4];
#pragma unroll
            for (int j = 0; j < 4; j++) {
                float v0 = f[2 * j], v1 = f[2 * j + 1];
                __nv_bfloat16 h0 = __float2bfloat16(v0);
                __nv_bfloat16 h1 = __float2bfloat16(v1);
                __nv_bfloat16 l0 = __float2bfloat16(v0 - __bfloat162float(h0));
                __nv_bfloat16 l1 = __float2bfloat16(v1 - __bfloat162float(h1));
                hw[j] = pack2(h0, h1);
                lw[j] = pack2(l0, l1);
            }
            int up = u ^ ((r >> 1) & 3);
            sA[r * 4 + up] = make_uint4(hw[0], hw[1], hw[2], hw[3]);
            sA[512 + r * 4 + up] = make_uint4(lw[0], lw[1], lw[2], lw[3]);
        }
        __syncthreads();

        int bbase = stage * 1024;
#pragma unroll
        for (int kh = 0; kh < 2; kh++) {
            unsigned ah[2][4], al[2][4];
#pragma unroll
            for (int s = 0; s < 2; s++) {
                int r = warp_m * 32 + s * 16 + (lane & 15);
                int u = kh * 2 + (lane >> 4);
                int up = u ^ ((r >> 1) & 3);
                LDSM_X4(ah[s], smem_u32(&sA[r * 4 + up]));
                LDSM_X4(al[s], smem_u32(&sA[512 + r * 4 + up]));
            }
            int nb = warp_n * 64;
#pragma unroll
            for (int i = 0; i < 4; i++) {
                int r = nb + i * 16 + (lane & 7) + ((lane >> 4) << 3);
                int u = kh * 2 + ((lane >> 3) & 1);
                int up = u ^ ((r >> 1) & 3);
                unsigned bh[4], bl[4];
                LDSM_X4(bh, smem_u32(&sB[bbase + r * 4 + up]));
                LDSM_X4(bl, smem_u32(&sB[bbase + 512 + r * 4 + up]));
#pragma unroll
                for (int s = 0; s < 2; s++) {
                    mma16816(acc[s][2 * i], ah[s][0], ah[s][1], ah[s][2], ah[s][3], bh[0], bh[1]);
                    mma16816(acc[s][2 * i], ah[s][0], ah[s][1], ah[s][2], ah[s][3], bl[0], bl[1]);
                    mma16816(acc[s][2 * i], al[s][0], al[s][1], al[s][2], al[s][3], bh[0], bh[1]);
                    mma16816(acc[s][2 * i + 1], ah[s][0], ah[s][1], ah[s][2], ah[s][3], bh[2], bh[3]);
                    mma16816(acc[s][2 * i + 1], ah[s][0], ah[s][1], ah[s][2], ah[s][3], bl[2], bl[3]);
                    mma16816(acc[s][2 * i + 1], al[s][0], al[s][1], al[s][2], al[s][3], bh[2], bh[3]);
                }
            }
        }
        __syncthreads();
    }

    // ---- epilogue ----
#pragma unroll
    for (int s = 0; s < 2; s++) {
        int grb = row0 + warp_m * 32 + s * 16 + (lane >> 2);
#pragma unroll
        for (int nt = 0; nt < 8; nt++) {
            int gc = col0 + warp_n * 64 + nt * 8 + (lane & 3) * 2;
#pragma unroll
            for (int half = 0; half < 2; half++) {
                int gr = grb + half * 8;
                if (gr >= M || gc >= NCOL) continue;
                float* crow = C + (long)gr * ldc;
                float v0 = acc[s][nt][half * 2 + 0] + (bias ? bias[gc] : 0.f);
                float v1 = acc[s][nt][half * 2 + 1] + (bias ? bias[gc + 1] : 0.f);
                if (mode == 1) {
                    v0 = fmaxf(v0, 0.f) * ls[gc] + crow[gc];
                    v1 = fmaxf(v1, 0.f) * ls[gc + 1] + crow[gc + 1];
                }
                crow[gc] = v0;
                crow[gc + 1] = v1;
                if (out16)
                    *(__half2*)(out16 + (size_t)gr * NCOL + gc) = __floats2half2_rn(v0, v1);
            }
        }
    }
}

// ------------------------- small utility kernels -------------------------
__global__ void zero_int(int* p, int n) {
    int gid = blockIdx.x * blockDim.x + threadIdx.x;
    if (gid < n) p[gid] = 0;
}

__global__ void hist_kernel(const int* __restrict__ idx, int* __restrict__ cnt, int n) {
    int gid = blockIdx.x * blockDim.x + threadIdx.x;
    if (gid < n) atomicAdd(&cnt[idx[gid]], 1);
}

__global__ void scan1_kernel(const int* __restrict__ in, int* __restrict__ outp1,
                             int* __restrict__ bsums, int n) {
    __shared__ int sh[1024];
    int t = threadIdx.x;
    long base = (long)blockIdx.x * 8192 + (long)t * 8;
    int v[8];
    int run = 0;
#pragma unroll
    for (int i = 0; i < 8; i++) {
        long idx = base + i;
        int x = (idx < n) ? in[idx] : 0;
        run += x;
        v[i] = run;
    }
    sh[t] = run;
    __syncthreads();
    int total = run;
    for (int off = 1; off < 1024; off <<= 1) {
        int y = (t >= off) ? sh[t - off] : 0;
        __syncthreads();
        sh[t] += y;
        __syncthreads();
    }
    int excl = sh[t] - total;
#pragma unroll
    for (int i = 0; i < 8; i++) {
        long idx = base + i;
        if (idx < n) outp1[idx + 1] = v[i] + excl;
    }
    if (t == 1023) bsums[blockIdx.x] = sh[1023];
    if (blockIdx.x == 0 && t == 0) outp1[0] = 0;
}

__global__ void scan2_kernel(int* bsums, int nb) {
    __shared__ int sh[1024];
    int t = threadIdx.x;
    int v = (t < nb) ? bsums[t] : 0;
    sh[t] = v;
    __syncthreads();
    for (int off = 1; off < 1024; off <<= 1) {
        int y = (t >= off) ? sh[t - off] : 0;
        __syncthreads();
        sh[t] += y;
        __syncthreads();
    }
    if (t < nb) bsums[t] = sh[t] - v;  // exclusive
}

__global__ void scan3_kernel(int* outp1, const int* __restrict__ bsums, int n) {
    int gid = blockIdx.x * blockDim.x + threadIdx.x;
    if (gid < n) outp1[gid + 1] += bsums[gid >> 13];
}

__global__ void copy_int(const int* __restrict__ a, int* __restrict__ b, int n) {
    int gid = blockIdx.x * blockDim.x + threadIdx.x;
    if (gid < n) b[gid] = a[gid];
}

__global__ void fill_adj_kernel(const int* __restrict__ src, const int* __restrict__ dst,
                                int* __restrict__ fill, int2* __restrict__ adj, int n) {
    int gid = blockIdx.x * blockDim.x + threadIdx.x;
    if (gid < n) {
        int d = dst[gid];
        int pos = atomicAdd(&fill[d], 1);
        adj[pos] = make_int2(src[gid], gid);
    }
}

// ------------------------- message passing (fp16 inputs, fp32 math) -------------------------
__global__ void msg16_kernel(const __half2* __restrict__ h16, const __half2* __restrict__ e16,
                             const int* __restrict__ rowptr, const int2* __restrict__ adj,
                             float* __restrict__ agg) {
    long gid = (long)blockIdx.x * blockDim.x + threadIdx.x;
    if (gid >= (long)NN * 100) return;
    int v = (int)(gid / 100);
    int f = (int)(gid - (long)v * 100);
    int b = rowptr[v], en = rowptr[v + 1];
    float mx0 = -3.4e38f, mx1 = -3.4e38f;
    float d0 = 0.f, d1 = 0.f, a0 = 0.f, a1 = 0.f;
    for (int p = b; p < en; p++) {
        int2 se = adj[p];
        float2 hh = __half22float2(h16[(long)se.x * 100 + f]);
        float2 ee = __half22float2(e16[(long)se.y * 100 + f]);
        float m0 = hh.x + ee.x;
        float m1 = hh.y + ee.y;
        float n0 = fmaxf(mx0, m0);
        float sc0 = __expf(mx0 - n0);
        float p0 = __expf(m0 - n0);
        d0 = d0 * sc0 + p0;
        a0 = a0 * sc0 + p0 * m0;
        mx0 = n0;
        float n1 = fmaxf(mx1, m1);
        float sc1 = __expf(mx1 - n1);
        float p1 = __expf(m1 - n1);
        d1 = d1 * sc1 + p1;
        a1 = a1 * sc1 + p1 * m1;
        mx1 = n1;
    }
    float2 r;
    r.x = (d0 > 0.f) ? a0 / d0 : 0.f;
    r.y = (d1 > 0.f) ? a1 / d1 : 0.f;
    *(float2*)(agg + (long)v * HD + 2 * f) = r;
}

// ------------------------- graph readout kernels -------------------------
__global__ void gsum_kernel(const float* __restrict__ h, const int* __restrict__ gptr,
                            float* __restrict__ g) {
    int gid = blockIdx.x * blockDim.x + threadIdx.x;
    if (gid >= NG * HD) return;
    int gg = gid / HD;
    int f = gid - gg * HD;
    int b = gptr[gg], e = gptr[gg + 1];
    float s = 0.f;
    for (int n = b; n < e; n++) s += h[(long)n * HD + f];
    g[gid] = s;
}

__global__ void z_kernel(const float* __restrict__ h, const float* __restrict__ g,
                         const int* __restrict__ n2g, const float* __restrict__ lw,
                         const float* __restrict__ lb, float* __restrict__ z) {
    int warp = (blockIdx.x * blockDim.x + threadIdx.x) >> 5;
    int lane = threadIdx.x & 31;
    if (warp >= NN) return;
    int gg = n2g[warp];
    const float* grow = g + (long)gg * HD;
    const float* hrow = h + (long)warp * HD;
    float s = 0.f;
    for (int f = lane; f < HD; f += 32)
        s += fmaxf(grow[f], 0.f) * lw[f] + hrow[f] * lw[HD + f];
#pragma unroll
    for (int o = 16; o; o >>= 1) s += __shfl_xor_sync(0xffffffffu, s, o);
    if (lane == 0) {
        float v = s + lb[0];
        z[warp] = (v > 0.f) ? v : 0.01f * v;  // leaky_relu
    }
}

__global__ void attn_kernel(const float* __restrict__ z, const int* __restrict__ gptr,
                            float* __restrict__ zmax, float* __restrict__ zden) {
    int warp = (blockIdx.x * blockDim.x + threadIdx.x) >> 5;
    int lane = threadIdx.x & 31;
    if (warp >= NG) return;
    int b = gptr[warp], e = gptr[warp + 1];
    float mx = -3.4e38f;
    for (int i = b + lane; i < e; i += 32) mx = fmaxf(mx, z[i]);
#pragma unroll
    for (int o = 16; o; o >>= 1) mx = fmaxf(mx, __shfl_xor_sync(0xffffffffu, mx, o));
    float s = 0.f;
    for (int i = b + lane; i < e; i += 32) s += __expf(z[i] - mx);
#pragma unroll
    for (int o = 16; o; o >>= 1) s += __shfl_xor_sync(0xffffffffu, s, o);
    if (lane == 0) {
        zmax[warp] = mx;
        zden[warp] = s;
    }
}

__global__ void ctx_kernel(const float* __restrict__ hv, const float* __restrict__ z,
                           const float* __restrict__ zmax, const float* __restrict__ zden,
                           const int* __restrict__ gptr, float* __restrict__ ctx) {
    int gid = blockIdx.x * blockDim.x + threadIdx.x;
    if (gid >= NG * HD) return;
    int gg = gid / HD;
    int f = gid - gg * HD;
    int b = gptr[gg], e = gptr[gg + 1];
    float zm = zmax[gg];
    float inv = 1.f / zden[gg];
    float s = 0.f;
    for (int n = b; n < e; n++)
        s += hv[(long)n * HD + f] * (__expf(z[n] - zm) * inv);
    ctx[gid] = (s > 0.f) ? s : (__expf(s) - 1.f);  // elu
}

__global__ void gru_kernel(const float* __restrict__ gi, const float* __restrict__ gh,
                           float* __restrict__ g) {
    int gid = blockIdx.x * blockDim.x + threadIdx.x;
    if (gid >= NG * HD) return;
    int gg = gid / HD;
    int f = gid - gg * HD;
    const float* gib = gi + gg * 600;
    const float* ghb = gh + gg * 600;
    float r = 1.f / (1.f + __expf(-(gib[f] + ghb[f])));
    float u = 1.f / (1.f + __expf(-(gib[200 + f] + ghb[200 + f])));
    float nn = tanhf(gib[400 + f] + r * ghb[400 + f]);
    g[gid] = (1.f - u) * nn + u * g[gid];
}

__global__ void out2_kernel(const float* __restrict__ tmp, const float* __restrict__ w2,
                            const float* __restrict__ b2, float* __restrict__ out) {
    int warp = (blockIdx.x * blockDim.x + threadIdx.x) >> 5;
    int lane = threadIdx.x & 31;
    if (warp >= NG) return;
    float s = 0.f;
    const float* row = tmp + (long)warp * 1024;
    for (int c = lane; c < 1024; c += 32) s += fmaxf(row[c], 0.f) * w2[c];
#pragma unroll
    for (int o = 16; o; o >>= 1) s += __shfl_xor_sync(0xffffffffu, s, o);
    if (lane == 0) out[warp] = s + b2[0];
}

// ------------------------- launch -------------------------
static __nv_bfloat16 *g_pwh, *g_pwl;

static void launch_gemm(int slot, const float* A, const float* bias, float* C,
                        int M, int K, int NCOL, int mode, const float* ls,
                        __half* out16) {
    dim3 grid((M + 127) / 128, (NCOL + 127) / 128);
    mma_gemm4<<<grid, 256, SM_TOT>>>(A, g_pwh + (size_t)slot * WSLOT,
                                     g_pwl + (size_t)slot * WSLOT, bias, C, M, K,
                                     NCOL, NCOL, mode, ls, out16);
}

extern "C" void kernel_launch(void* const* d_in, const int* in_sizes, int n_in,
                              void* d_out, int out_size) {
    const float* node_feats = (const float*)d_in[0];
    const float* edge_feats = (const float*)d_in[1];
    const int* src = (const int*)d_in[2];
    const int* dst = (const int*)d_in[3];
    const int* n2g = (const int*)d_in[4];
    const float* atom_W = (const float*)d_in[5];
    const float* atom_b = (const float*)d_in[6];
    const float* bond_W = (const float*)d_in[7];
    const float* bond_b = (const float*)d_in[8];
    const float* mlp_W = (const float*)d_in[9];
    const float* mlp_b = (const float*)d_in[10];
    const float* ls = (const float*)d_in[11];
    const float* logit_W = (const float*)d_in[12];
    const float* logit_b = (const float*)d_in[13];
    const float* proj_W = (const float*)d_in[14];
    const float* proj_b = (const float*)d_in[15];
    const float* gru_Wih = (const float*)d_in[16];
    const float* gru_Whh = (const float*)d_in[17];
    const float* gru_bih = (const float*)d_in[18];
    const float* gru_bhh = (const float*)d_in[19];
    const float* out1_W = (const float*)d_in[20];
    const float* out1_b = (const float*)d_in[21];
    const float* out2_W = (const float*)d_in[22];
    const float* out2_b = (const float*)d_in[23];
    float* out = (float*)d_out;

    cudaFuncSetAttribute(mma_gemm4, cudaFuncAttributeMaxDynamicSharedMemorySize, SM_TOT);

    float *ph, *pe, *pagg, *phv, *pg, *pctx, *pgi, *pgh, *pt1, *pz, *pzmax, *pzden;
    int *pcnt, *prow, *pfill, *pgcnt, *pgptr, *pbs;
    int2* padj;
    __half *ph16, *pe16;
    cudaGetSymbolAddress((void**)&ph, d_h);
    cudaGetSymbolAddress((void**)&pe, d_e);
    cudaGetSymbolAddress((void**)&pagg, d_agg);
    cudaGetSymbolAddress((void**)&phv, d_hv);
    cudaGetSymbolAddress((void**)&pg, d_g);
    cudaGetSymbolAddress((void**)&pctx, d_ctx);
    cudaGetSymbolAddress((void**)&pgi, d_gi);
    cudaGetSymbolAddress((void**)&pgh, d_gh);
    cudaGetSymbolAddress((void**)&pt1, d_t1);
    cudaGetSymbolAddress((void**)&pz, d_z);
    cudaGetSymbolAddress((void**)&pzmax, d_zmax);
    cudaGetSymbolAddress((void**)&pzden, d_zden);
    cudaGetSymbolAddress((void**)&pcnt, d_cnt);
    cudaGetSymbolAddress((void**)&prow, d_rowptr);
    cudaGetSymbolAddress((void**)&pfill, d_fill);
    cudaGetSymbolAddress((void**)&pgcnt, d_gcnt);
    cudaGetSymbolAddress((void**)&pgptr, d_gptr);
    cudaGetSymbolAddress((void**)&pbs, d_bsums);
    cudaGetSymbolAddress((void**)&padj, d_adj);
    cudaGetSymbolAddress((void**)&ph16, d_h16);
    cudaGetSymbolAddress((void**)&pe16, d_e16);
    cudaGetSymbolAddress((void**)&g_pwh, d_wall_h);
    cudaGetSymbolAddress((void**)&g_pwl, d_wall_l);

    // ---- slot table ----
    WTable T;
    T.s[0] = {atom_W, 74, HD, HD};
    T.s[1] = {bond_W, 12, HD, HD};
    for (int i = 0; i < NLAYERS; i++) T.s[2 + i] = {mlp_W + (size_t)i * HD * HD, HD, HD, HD};
    for (int t = 0; t < TSTEPS; t++) {
        T.s[7 + t] = {proj_W + (size_t)t * HD * HD, HD, HD, HD};
        T.s[9 + t] = {gru_Wih + (size_t)t * HD * 600, HD, 600, 600};
        T.s[11 + t] = {gru_Whh + (size_t)t * HD * 600, HD, 600, 600};
    }
    T.s[13] = {out1_W, HD, 1024, 1024};

    // launch order chosen so the node-encoder GEMM is our 4th launch (ncu capture)
    wconv_all<<<(NSLOTS * WSLOT + 255) / 256, 256>>>(T, g_pwh, g_pwl);       // 1
    zero_int<<<(NN + 255) / 256, 256>>>(pcnt, NN);                           // 2
    hist_kernel<<<(NE + 255) / 256, 256>>>(dst, pcnt, NE);                   // 3
    launch_gemm(0, node_feats, atom_b, ph, NN, 74, HD, 0, nullptr, ph16);    // 4 <- capture
    launch_gemm(1, edge_feats, bond_b, pe, NE, 12, HD, 0, nullptr, pe16);    // 5

    // ---- CSR by dst (cont.) ----
    int nb1 = (NN + 8191) / 8192;
    scan1_kernel<<<nb1, 1024>>>(pcnt, prow, pbs, NN);
    scan2_kernel<<<1, 1024>>>(pbs, nb1);
    scan3_kernel<<<(NN + 255) / 256, 256>>>(prow, pbs, NN);
    copy_int<<<(NN + 255) / 256, 256>>>(prow, pfill, NN);
    fill_adj_kernel<<<(NE + 255) / 256, 256>>>(src, dst, pfill, padj, NE);

    // ---- graph offsets ----
    zero_int<<<(NG + 255) / 256, 256>>>(pgcnt, NG);
    hist_kernel<<<(NN + 255) / 256, 256>>>(n2g, pgcnt, NN);
    scan1_kernel<<<1, 1024>>>(pgcnt, pgptr, pbs, NG);
    scan2_kernel<<<1, 1024>>>(pbs, 1);
    scan3_kernel<<<(NG + 255) / 256, 256>>>(pgptr, pbs, NG);

    // ---- message passing layers ----
    long nthr = (long)NN * 100;
    int mblocks = (int)((nthr + 255) / 256);
    for (int i = 0; i < NLAYERS; i++) {
        msg16_kernel<<<mblocks, 256>>>((const __half2*)ph16, (const __half2*)pe16,
                                       prow, padj, pagg);
        launch_gemm(2 + i, pagg, mlp_b + i * HD, ph, NN, HD, HD, 1, ls + i * HD, ph16);
    }

    // ---- readout ----
    gsum_kernel<<<(NG * HD + 255) / 256, 256>>>(ph, pgptr, pg);
    for (int t = 0; t < TSTEPS; t++) {
        z_kernel<<<(NN * 32 + 255) / 256, 256>>>(ph, pg, n2g, logit_W + t * 2 * HD,
                                                 logit_b + t, pz);
        attn_kernel<<<(NG * 32 + 255) / 256, 256>>>(pz, pgptr, pzmax, pzden);
        launch_gemm(7 + t, ph, proj_b + t * HD, phv, NN, HD, HD, 0, nullptr, nullptr);
        ctx_kernel<<<(NG * HD + 255) / 256, 256>>>(phv, pz, pzmax, pzden, pgptr, pctx);
        launch_gemm(9 + t, pctx, gru_bih + t * 600, pgi, NG, HD, 600, 0, nullptr, nullptr);
        launch_gemm(11 + t, pg, gru_bhh + t * 600, pgh, NG, HD, 600, 0, nullptr, nullptr);
        gru_kernel<<<(NG * HD + 255) / 256, 256>>>(pgi, pgh, pg);
    }

    launch_gemm(13, pg, out1_b, pt1, NG, HD, 1024, 0, nullptr, nullptr);
    out2_kernel<<<(NG * 32 + 255) / 256, 256>>>(pt1, out2_W, out2_b, out);
}